// round 11
// baseline (speedup 1.0000x reference)
#include <cuda_runtime.h>
#include <cuda_fp16.h>
#include <math.h>
#include <stdint.h>

#define EPS 1e-5f

// ================= device scratch (no runtime allocation allowed) ==============
__device__ float g_wm1[3456], g_wv1[3456];

// weight variants, K-major [3][COUT*9*CIN] fp16 : 0=m_hi 1=m_lo 2=v
__device__ __half g_w2q[442368];
__device__ __half g_w3q[884736];
__device__ __half g_w4q[1769472];
__device__ __half g_w5q[3538944];
__device__ __half g_w6q[7077888];

// activation NHWC fp16 planes: [3][N*H*W*C] : 0=x_hi 1=x_lo 2=s
__device__ __half g_p1[100663296];  // (256,32,32,128)
__device__ __half g_p2[25165824];   // (256,16,16,128)
__device__ __half g_p3[50331648];   // (256,16,16,256)
__device__ __half g_p4[12582912];   // (256,8,8,256)
__device__ __half g_p5[25165824];   // (256,8,8,512)

__device__ float g_z6[2097152];   // [256,512,4,4] fp32 NCHW
__device__ float g_zbn[2097152];
__device__ float g_fc1o[262144];
__device__ float g_bnscale[512], g_bnshift[512];

// ================= packed f32x2 helpers (SIMT L1) ==============================
__device__ __forceinline__ unsigned long long bcast2(float x) {
    unsigned long long r; unsigned u = __float_as_uint(x);
    asm("mov.b64 %0, {%1, %1};" : "=l"(r) : "r"(u));
    return r;
}
__device__ __forceinline__ unsigned long long mul2(unsigned long long a, unsigned long long b) {
    unsigned long long d;
    asm("mul.rn.f32x2 %0, %1, %2;" : "=l"(d) : "l"(a), "l"(b));
    return d;
}
__device__ __forceinline__ void fma2(unsigned long long& d, unsigned long long a, unsigned long long b) {
    asm("fma.rn.f32x2 %0, %1, %2, %0;" : "+l"(d) : "l"(a), "l"(b));
}
__device__ __forceinline__ void unpack2(unsigned long long v, float& lo, float& hi) {
    unsigned ulo, uhi;
    asm("mov.b64 {%0, %1}, %2;" : "=r"(ulo), "=r"(uhi) : "l"(v));
    lo = __uint_as_float(ulo); hi = __uint_as_float(uhi);
}

// fp16 pair pack: low half = first element
__device__ __forceinline__ uint32_t pkh2(float a, float b) {
    uint32_t lo = (uint32_t)__half_as_ushort(__float2half_rn(a));
    uint32_t hi = (uint32_t)__half_as_ushort(__float2half_rn(b));
    return lo | (hi << 16);
}

// mma.sync m16n8k16 fp16 -> f32
#define MMA16816(C, A, B) asm volatile( \
    "mma.sync.aligned.m16n8k16.row.col.f32.f16.f16.f32 " \
    "{%0,%1,%2,%3},{%4,%5,%6,%7},{%8,%9},{%0,%1,%2,%3};" \
    : "+f"((C)[0]), "+f"((C)[1]), "+f"((C)[2]), "+f"((C)[3]) \
    : "r"((A)[0]), "r"((A)[1]), "r"((A)[2]), "r"((A)[3]), \
      "r"((B)[0]), "r"((B)[1]))

#define LDMX4(R, ADDR) asm volatile( \
    "ldmatrix.sync.aligned.m8n8.x4.shared.b16 {%0,%1,%2,%3}, [%4];" \
    : "=r"((R)[0]), "=r"((R)[1]), "=r"((R)[2]), "=r"((R)[3]) : "r"(ADDR))

// 16B async copy, global -> shared, L1-bypass; sz=0 zero-fills
__device__ __forceinline__ void cpa16(uint32_t dst, const void* src, int sz) {
    asm volatile("cp.async.cg.shared.global [%0], [%1], 16, %2;"
                 :: "r"(dst), "l"(src), "r"(sz));
}
__device__ __forceinline__ void cpa_commit() {
    asm volatile("cp.async.commit_group;" ::: "memory");
}
__device__ __forceinline__ void cpa_wait1() {
    asm volatile("cp.async.wait_group 1;" ::: "memory");
}
__device__ __forceinline__ void cpa_wait0() {
    asm volatile("cp.async.wait_group 0;" ::: "memory");
}

// ================= weight preprocessing (one launch) ===========================
__global__ void prepw(const float* __restrict__ a1, const float* __restrict__ b1,
                      const float* __restrict__ a2, const float* __restrict__ b2,
                      const float* __restrict__ a3, const float* __restrict__ b3,
                      const float* __restrict__ a4, const float* __restrict__ b4,
                      const float* __restrict__ a5, const float* __restrict__ b5,
                      const float* __restrict__ a6, const float* __restrict__ b6)
{
    int i = blockIdx.x * blockDim.x + threadIdx.x;
    if (i >= 4574592) return;

    const float *A, *Bp; int j, cin; __half* WQ; int wplane; bool l1 = false;
    if (i < 150912) {
        if (i < 3456) { A = a1; Bp = b1; j = i; l1 = true; cin = 3; WQ = nullptr; wplane = 0; }
        else          { A = a2; Bp = b2; j = i - 3456;   cin = 128; WQ = g_w2q; wplane = 147456; }
    } else if (i < 1035648) {
        if (i < 445824) { A = a3; Bp = b3; j = i - 150912; cin = 128; WQ = g_w3q; wplane = 294912; }
        else            { A = a4; Bp = b4; j = i - 445824; cin = 256; WQ = g_w4q; wplane = 589824; }
    } else {
        if (i < 2215296) { A = a5; Bp = b5; j = i - 1035648; cin = 256; WQ = g_w5q; wplane = 1179648; }
        else             { A = a6; Bp = b6; j = i - 2215296; cin = 512; WQ = g_w6q; wplane = 2359296; }
    }
    float p0 = 1.f / (1.f + expf(-A[j]));
    float sb = 1.f / (1.f + expf(-Bp[j]));
    float p1 = (1.f - p0) * sb;
    float m  = 2.f * p1 + p0 - 1.f;
    float v  = (1.f - p0) - m * m;
    if (l1) { g_wm1[j] = m; g_wv1[j] = v; return; }
    int k9 = cin * 9;
    int co  = j / k9;
    int r   = j - co * k9;
    int ci  = r / 9;
    int tap = r - ci * 9;
    int o   = co * k9 + tap * cin + ci;
    __half mh = __float2half_rn(m);
    WQ[o]              = mh;
    WQ[wplane + o]     = __float2half_rn(m - __half2float(mh));
    WQ[2 * wplane + o] = __float2half_rn(v);
}

// ================= L1 conv (SIMT, CIN=3) -> NHWC fp16 planes ===================
__global__ void __launch_bounds__(128)
conv1(const float* __restrict__ in, const float* __restrict__ bias,
      __half* __restrict__ pout)
{
    constexpr int CIN = 3, HIN = 32, WIN = 32, CK = 3;
    constexpr int TCO = 32, IPH = 10, IPW = 12;
    constexpr int XS_N = 2 * CK * IPH * IPW;
    constexpr int WS_N = CK * 9 * TCO;
    constexpr int NXV = 10, NF4 = 3, CP = 2, PX_T = 8;
    constexpr int OPLANE = 256 * 32 * 32 * 128;

    __shared__ __align__(16) float xs[XS_N];
    __shared__ __align__(16) float wsm[WS_N];
    __shared__ __align__(16) float wsv[WS_N];

    const int tid = threadIdx.x;
    const int tileX = blockIdx.x % 4, tileY = blockIdx.x / 4;
    const int coBase = blockIdx.y * TCO;
    const int nBase  = blockIdx.z * 2;
    const int oy0 = tileY * 8, ox0 = tileX * 8;

    const int co0 = (tid % 8) * 4;
    const int pg  = tid / 8;
    const int img = pg / 8;
    const int py  = pg % 8;

    unsigned long long aM[CP][PX_T], aV[CP][PX_T];
    #pragma unroll
    for (int p = 0; p < CP; p++)
        #pragma unroll
        for (int i = 0; i < PX_T; i++) { aM[p][i] = 0ull; aV[p][i] = 0ull; }

    for (int idx = tid; idx < XS_N; idx += 128) {
        int im = idx / (CK * IPH * IPW);
        int r  = idx - im * (CK * IPH * IPW);
        int ck = r / (IPH * IPW);
        int r2 = r - ck * (IPH * IPW);
        int iy = r2 / IPW;
        int ix = r2 - iy * IPW;
        int gy = oy0 - 1 + iy, gx = ox0 - 1 + ix;
        float v = 0.f;
        if (gy >= 0 && gy < HIN && gx >= 0 && gx < WIN)
            v = in[(((nBase + im) * CIN + ck) * HIN + gy) * WIN + gx];
        xs[idx] = v;
    }
    for (int idx = tid; idx < WS_N; idx += 128) {
        int ck  = idx / (9 * TCO);
        int rm  = idx - ck * (9 * TCO);
        int tap = rm / TCO;
        int co  = rm - tap * TCO;
        int g = ((coBase + co) * CIN + ck) * 9 + tap;
        wsm[idx] = g_wm1[g];
        wsv[idx] = g_wv1[g];
    }
    __syncthreads();

    #pragma unroll 1
    for (int ck = 0; ck < CK; ck++) {
        #pragma unroll
        for (int ky = 0; ky < 3; ky++) {
            const float* xrow = &xs[((img * CK + ck) * IPH + (py + ky)) * IPW];
            float4 f4[NF4];
            #pragma unroll
            for (int j = 0; j < NF4; j++)
                f4[j] = reinterpret_cast<const float4*>(xrow)[j];
            const float* xv = reinterpret_cast<const float*>(f4);
            unsigned long long xp[NXV], xxp[NXV];
            #pragma unroll
            for (int j = 0; j < NXV; j++) {
                xp[j]  = bcast2(xv[j]);
                xxp[j] = mul2(xp[j], xp[j]);
            }
            #pragma unroll
            for (int kx = 0; kx < 3; kx++) {
                const int tap = ky * 3 + kx;
                ulonglong2 m2 = *reinterpret_cast<const ulonglong2*>(&wsm[(ck * 9 + tap) * TCO + co0]);
                ulonglong2 v2 = *reinterpret_cast<const ulonglong2*>(&wsv[(ck * 9 + tap) * TCO + co0]);
                #pragma unroll
                for (int i = 0; i < PX_T; i++) {
                    fma2(aM[0][i], m2.x, xp[kx + i]);
                    fma2(aM[1][i], m2.y, xp[kx + i]);
                    fma2(aV[0][i], v2.x, xxp[kx + i]);
                    fma2(aV[1][i], v2.y, xxp[kx + i]);
                }
            }
        }
    }

    const int n = nBase + img;
    const int oy = oy0 + py;
    #pragma unroll
    for (int p = 0; p < CP; p++) {
        const int cA = coBase + co0 + 2 * p;
        const float bA = bias[cA], bB = bias[cA + 1];
        #pragma unroll
        for (int i = 0; i < PX_T; i++) {
            float mA, mB, vA, vB;
            unpack2(aM[p][i], mA, mB);
            unpack2(aV[p][i], vA, vB);
            mA += bA; mB += bB;
            float hA = erff(mA * rsqrtf(2.f * (vA + EPS)));
            float hB = erff(mB * rsqrtf(2.f * (vB + EPS)));
            int oi = ((n * 32 + oy) * 32 + (ox0 + i)) * 128 + cA;
            float lA = hA - __half2float(__float2half_rn(hA));
            float lB = hB - __half2float(__float2half_rn(hB));
            *(uint32_t*)&pout[oi]              = pkh2(hA, hB);
            *(uint32_t*)&pout[OPLANE + oi]     = pkh2(lA, lB);
            *(uint32_t*)&pout[2 * OPLANE + oi] = pkh2(hA * hA, hB * hB);
        }
    }
}

// ================= mma.sync conv layers 2-6 (v4: hoisted fragments) ============
// Block: 128px x 128co, 8 warps (256 thr), warp = 64px x 32co (mt=4, nt=4).
// Double-buffered cp.async pipeline + all-ks-fragments hoisted before MMAs.
// m = x_hi*wm_hi + x_lo*wm_hi + x_hi*wm_lo ; v = s*wv
template<int CIN, int COUT, int HIN, int WIN, int S, bool LAST>
__global__ void __launch_bounds__(256)
conv_mma(const __half* __restrict__ wq,    // [3][COUT*9CIN]
         const __half* __restrict__ pin,   // [3 planes][256*HIN*WIN*CIN]
         const float* __restrict__ bias,
         __half* __restrict__ pout,        // planes (if !LAST)
         float* __restrict__ zout,         // NCHW fp32 (if LAST)
         const float* __restrict__ noise)
{
    constexpr int HO = HIN / S, WO = WIN / S;
    constexpr int PIX = HO * WO;
    constexpr int CG = CIN / 64;
    constexpr int NS = 9 * CG;
    constexpr int K9 = 9 * CIN;
    constexpr int WPLANE = COUT * K9;
    constexpr int IPLANE = 256 * HIN * WIN * CIN;
    constexpr int OPLANE = 256 * HO * WO * COUT;
    constexpr int AST = 72;                  // padded row stride (144 B)
    constexpr int APL = 128 * AST;           // A plane: 128 pixel rows
    constexpr int BPL = 128 * AST;           // B plane: 128 cout rows
    constexpr uint32_t BUF = (uint32_t)(3 * APL + 3 * BPL) * 2;  // 110592 B / stage

    extern __shared__ __align__(16) __half sm[];

    const int tid = threadIdx.x;
    const int wid = tid >> 5, lid = tid & 31;
    const int g = lid >> 2, t = lid & 3;
    const int wpx = wid >> 2, wco = wid & 3;     // 2 px-halves x 4 co-quarters
    const int pixBase = blockIdx.x * 128;
    const int coBase  = blockIdx.y * 128;

    const uint32_t smb = (uint32_t)__cvta_generic_to_shared(sm);
    const int arow = (lid & 7) + ((lid >> 3) & 1) * 8;
    const int achk = ((lid >> 4) & 1) * 8;
    const int brow = (lid & 7) + ((lid >> 4) & 1) * 8;
    const int bchk = ((lid >> 3) & 1) * 8;
    const uint32_t aAddr0 = smb + (uint32_t)(((wpx * 64 + arow) * AST + achk) * 2);
    const uint32_t bAddr0 = smb + (uint32_t)(3 * APL * 2) +
                            (uint32_t)(((wco * 32 + brow) * AST + bchk) * 2);

    // staging: 3 A planes x 128 rows + 3 B variants x 128 rows = 768 row jobs
    auto stage = [&](int s, uint32_t bofs) {
        const int tap = s / CG, cg = s - tap * CG;
        const int ky = tap / 3, kx = tap - ky * 3;
        const int c0 = cg * 64;
        #pragma unroll 1
        for (int j = tid; j < 768; j += 256) {
            if (j < 384) {
                const int pl = j >> 7, row = j & 127;
                const int gp = pixBase + row;
                const int n  = gp / PIX;
                const int r  = gp - n * PIX;
                const int oy = r / WO, ox = r - (r / WO) * WO;
                const int iy = oy * S - 1 + ky, ix = ox * S - 1 + kx;
                uint32_t dst = smb + bofs + (uint32_t)((pl * APL + row * AST) * 2);
                const bool ok = (iy >= 0 && iy < HIN && ix >= 0 && ix < WIN);
                const __half* src = ok
                    ? pin + (size_t)pl * IPLANE + ((size_t)(n * HIN + iy) * WIN + ix) * CIN + c0
                    : pin;
                const int sz = ok ? 16 : 0;
                #pragma unroll
                for (int q = 0; q < 8; q++)
                    cpa16(dst + q * 16, src + q * 8, sz);
            } else {
                const int jj = j - 384;
                const int var = jj >> 7, row = jj & 127;
                const __half* src = wq + (size_t)var * WPLANE +
                                    (size_t)(coBase + row) * K9 + tap * CIN + c0;
                uint32_t dst = smb + bofs + (uint32_t)((3 * APL + var * BPL + row * AST) * 2);
                #pragma unroll
                for (int q = 0; q < 8; q++)
                    cpa16(dst + q * 16, src + q * 8, 16);
            }
        }
    };

    float accM[4][4][4], accV[4][4][4];
    #pragma unroll
    for (int mt = 0; mt < 4; mt++)
        #pragma unroll
        for (int nt = 0; nt < 4; nt++)
            #pragma unroll
            for (int e = 0; e < 4; e++) { accM[mt][nt][e] = 0.f; accV[mt][nt][e] = 0.f; }

    stage(0, 0);
    cpa_commit();

    #pragma unroll 1
    for (int s = 0; s < NS; s++) {
        if (s + 1 < NS) {
            stage(s + 1, (uint32_t)((s + 1) & 1) * BUF);
            cpa_commit();
            cpa_wait1();
        } else {
            cpa_wait0();
        }
        __syncthreads();

        const uint32_t bofs = (uint32_t)(s & 1) * BUF;
        #pragma unroll
        for (int ks = 0; ks < 4; ks++) {
            const uint32_t ksb = (uint32_t)(ks * 32) + bofs;
            // ---- hoist ALL fragments for this k-step before any MMA ----
            uint32_t bmh[2][4], bml[2][4], bv_[2][4];
            #pragma unroll
            for (int ntp = 0; ntp < 2; ntp++) {
                const uint32_t b0 = bAddr0 + (uint32_t)(ntp * 16 * AST * 2) + ksb;
                LDMX4(bmh[ntp], b0);
                LDMX4(bml[ntp], b0 + (uint32_t)(BPL * 2));
                LDMX4(bv_[ntp], b0 + (uint32_t)(2 * BPL * 2));
            }
            uint32_t axh[4][4], axl[4][4], as_[4][4];
            #pragma unroll
            for (int mt = 0; mt < 4; mt++) {
                const uint32_t a0 = aAddr0 + (uint32_t)(mt * 16 * AST * 2) + ksb;
                LDMX4(axh[mt], a0);
                LDMX4(axl[mt], a0 + (uint32_t)(APL * 2));
                LDMX4(as_[mt], a0 + (uint32_t)(2 * APL * 2));
            }
            // ---- 64 MMAs, all operands already in flight ----
            #pragma unroll
            for (int mt = 0; mt < 4; mt++)
                #pragma unroll
                for (int nt = 0; nt < 4; nt++) {
                    const int ntp = nt >> 1, o = (nt & 1) * 2;
                    MMA16816(accM[mt][nt], axh[mt], &bmh[ntp][o]);
                    MMA16816(accM[mt][nt], axl[mt], &bmh[ntp][o]);
                    MMA16816(accM[mt][nt], axh[mt], &bml[ntp][o]);
                    MMA16816(accV[mt][nt], as_[mt], &bv_[ntp][o]);
                }
        }
        __syncthreads();
    }

    // ---- epilogue ----
    #pragma unroll
    for (int mt = 0; mt < 4; mt++)
        #pragma unroll
        for (int nt = 0; nt < 4; nt++) {
            const int co0 = coBase + wco * 32 + nt * 8 + 2 * t;
            const float b0 = bias[co0], b1 = bias[co0 + 1];
            #pragma unroll
            for (int h2 = 0; h2 < 2; h2++) {
                const int gp = pixBase + wpx * 64 + mt * 16 + g + h2 * 8;
                float m0 = accM[mt][nt][2 * h2]     + b0;
                float m1 = accM[mt][nt][2 * h2 + 1] + b1;
                float v0 = accV[mt][nt][2 * h2];
                float v1 = accV[mt][nt][2 * h2 + 1];
                const int n = gp / PIX;
                const int r = gp - n * PIX;
                const int oy = r / WO, ox = r - (r / WO) * WO;
                if (LAST) {
                    int o0 = ((n * COUT + co0) * HO + oy) * WO + ox;
                    int o1 = o0 + HO * WO;
                    zout[o0] = m0 + sqrtf(v0 + EPS) * noise[o0];
                    zout[o1] = m1 + sqrtf(v1 + EPS) * noise[o1];
                } else {
                    float h0 = erff(m0 * rsqrtf(2.f * (v0 + EPS)));
                    float h1 = erff(m1 * rsqrtf(2.f * (v1 + EPS)));
                    float l0 = h0 - __half2float(__float2half_rn(h0));
                    float l1 = h1 - __half2float(__float2half_rn(h1));
                    int oi = ((n * HO + oy) * WO + ox) * COUT + co0;
                    *(uint32_t*)&pout[oi]              = pkh2(h0, h1);
                    *(uint32_t*)&pout[OPLANE + oi]     = pkh2(l0, l1);
                    *(uint32_t*)&pout[2 * OPLANE + oi] = pkh2(h0 * h0, h1 * h1);
                }
            }
        }
}

// ================= batchnorm / FC ==============================================
__global__ void bn_stats(const float* __restrict__ z, const float* __restrict__ gamma,
                         const float* __restrict__ beta, float* __restrict__ scale,
                         float* __restrict__ shift)
{
    __shared__ double ssum[256], ssq[256];
    int c = blockIdx.x, t = threadIdx.x;
    double s = 0.0, s2 = 0.0;
    for (int i = t; i < 4096; i += 256) {
        int n = i >> 4, qq = i & 15;
        float v = z[(n * 512 + c) * 16 + qq];
        s += v; s2 += (double)v * v;
    }
    ssum[t] = s; ssq[t] = s2;
    __syncthreads();
    for (int off = 128; off > 0; off >>= 1) {
        if (t < off) { ssum[t] += ssum[t + off]; ssq[t] += ssq[t + off]; }
        __syncthreads();
    }
    if (t == 0) {
        double mean = ssum[0] / 4096.0;
        double var  = ssq[0] / 4096.0 - mean * mean;
        float sc = gamma[c] * rsqrtf((float)var + EPS);
        scale[c] = sc;
        shift[c] = beta[c] - (float)mean * sc;
    }
}

__global__ void bn_norm(const float* __restrict__ z, const float* __restrict__ scale,
                        const float* __restrict__ shift, float* __restrict__ out)
{
    int idx = blockIdx.x * blockDim.x + threadIdx.x;
    if (idx < 256 * 8192) {
        int c = (idx >> 4) & 511;
        float v = z[idx] * scale[c] + shift[c];
        out[idx] = v > 0.f ? v : 0.f;
    }
}

__global__ void __launch_bounds__(256)
fc1_kernel(const float* __restrict__ A, const float* __restrict__ W,
           const float* __restrict__ bias, float* __restrict__ C)
{
    __shared__ float As[64][33];
    __shared__ float Ws[64][33];
    const int t = threadIdx.x;
    const int mBlk = blockIdx.y * 64, nBlk = blockIdx.x * 64;
    const int msub = (t % 16) * 4, nsub = (t / 16) * 4;
    float acc[4][4];
    #pragma unroll
    for (int i = 0; i < 4; i++)
        #pragma unroll
        for (int j = 0; j < 4; j++) acc[i][j] = 0.f;

    for (int k0 = 0; k0 < 8192; k0 += 32) {
        for (int i = t; i < 64 * 32; i += 256) {
            int r = i >> 5, kk = i & 31;
            As[r][kk] = A[(mBlk + r) * 8192 + k0 + kk];
            Ws[r][kk] = W[(nBlk + r) * 8192 + k0 + kk];
        }
        __syncthreads();
        #pragma unroll
        for (int kk = 0; kk < 32; kk++) {
            float a0 = As[msub][kk], a1 = As[msub + 1][kk], a2 = As[msub + 2][kk], a3 = As[msub + 3][kk];
            float w0 = Ws[nsub][kk], w1 = Ws[nsub + 1][kk], w2 = Ws[nsub + 2][kk], w3 = Ws[nsub + 3][kk];
            acc[0][0] += a0 * w0; acc[0][1] += a0 * w1; acc[0][2] += a0 * w2; acc[0][3] += a0 * w3;
            acc[1][0] += a1 * w0; acc[1][1] += a1 * w1; acc[1][2] += a1 * w2; acc[1][3] += a1 * w3;
            acc[2][0] += a2 * w0; acc[2][1] += a2 * w1; acc[2][2] += a2 * w2; acc[2][3] += a2 * w3;
            acc[3][0] += a3 * w0; acc[3][1] += a3 * w1; acc[3][2] += a3 * w2; acc[3][3] += a3 * w3;
        }
        __syncthreads();
    }
    #pragma unroll
    for (int i = 0; i < 4; i++)
        #pragma unroll
        for (int j = 0; j < 4; j++) {
            float v = acc[i][j] + bias[nBlk + nsub + j];
            C[(mBlk + msub + i) * 1024 + nBlk + nsub + j] = v > 0.f ? v : 0.f;
        }
}

__global__ void fc2_kernel(const float* __restrict__ A, const float* __restrict__ W,
                           const float* __restrict__ bias, float* __restrict__ out)
{
    int idx = blockIdx.x * blockDim.x + threadIdx.x;
    if (idx >= 2560) return;
    int n = idx / 10, j = idx - n * 10;
    const float* a = A + n * 1024;
    const float* w = W + j * 1024;
    float s = bias[j];
    for (int k = 0; k < 1024; k += 4)
        s += a[k] * w[k] + a[k + 1] * w[k + 1] + a[k + 2] * w[k + 2] + a[k + 3] * w[k + 3];
    out[idx] = s;
}

// ================= launch ======================================================
extern "C" void kernel_launch(void* const* d_in, const int* in_sizes, int n_in,
                              void* d_out, int out_size)
{
    (void)in_sizes; (void)n_in; (void)out_size;
    const float* x = (const float*)d_in[0];
    const float* a[6]  = {(const float*)d_in[1],  (const float*)d_in[4],  (const float*)d_in[7],
                          (const float*)d_in[10], (const float*)d_in[13], (const float*)d_in[16]};
    const float* bt[6] = {(const float*)d_in[2],  (const float*)d_in[5],  (const float*)d_in[8],
                          (const float*)d_in[11], (const float*)d_in[14], (const float*)d_in[17]};
    const float* cb[6] = {(const float*)d_in[3],  (const float*)d_in[6],  (const float*)d_in[9],
                          (const float*)d_in[12], (const float*)d_in[15], (const float*)d_in[18]};
    const float* gamma = (const float*)d_in[19];
    const float* beta  = (const float*)d_in[20];
    const float* fc1w  = (const float*)d_in[21];
    const float* fc1b  = (const float*)d_in[22];
    const float* fc2w  = (const float*)d_in[23];
    const float* fc2b  = (const float*)d_in[24];
    const float* noise = (const float*)d_in[25];

    __half *w2q, *w3q, *w4q, *w5q, *w6q, *p1, *p2, *p3, *p4, *p5;
    cudaGetSymbolAddress((void**)&w2q, g_w2q);
    cudaGetSymbolAddress((void**)&w3q, g_w3q);
    cudaGetSymbolAddress((void**)&w4q, g_w4q);
    cudaGetSymbolAddress((void**)&w5q, g_w5q);
    cudaGetSymbolAddress((void**)&w6q, g_w6q);
    cudaGetSymbolAddress((void**)&p1, g_p1);
    cudaGetSymbolAddress((void**)&p2, g_p2);
    cudaGetSymbolAddress((void**)&p3, g_p3);
    cudaGetSymbolAddress((void**)&p4, g_p4);
    cudaGetSymbolAddress((void**)&p5, g_p5);

    float *z6, *zbn, *fc1o, *scale, *shift;
    cudaGetSymbolAddress((void**)&z6,  g_z6);
    cudaGetSymbolAddress((void**)&zbn, g_zbn);
    cudaGetSymbolAddress((void**)&fc1o, g_fc1o);
    cudaGetSymbolAddress((void**)&scale, g_bnscale);
    cudaGetSymbolAddress((void**)&shift, g_bnshift);

    constexpr int SMEM_MMA = 2 * (3 * 128 + 3 * 128) * 72 * 2;   // 221184 B
    auto k2 = conv_mma<128, 128, 32, 32, 2, false>;
    auto k3 = conv_mma<128, 256, 16, 16, 1, false>;
    auto k4 = conv_mma<256, 256, 16, 16, 2, false>;
    auto k5 = conv_mma<256, 512, 8,  8,  1, false>;
    auto k6 = conv_mma<512, 512, 8,  8,  2, true>;
    cudaFuncSetAttribute(k2, cudaFuncAttributeMaxDynamicSharedMemorySize, SMEM_MMA);
    cudaFuncSetAttribute(k3, cudaFuncAttributeMaxDynamicSharedMemorySize, SMEM_MMA);
    cudaFuncSetAttribute(k4, cudaFuncAttributeMaxDynamicSharedMemorySize, SMEM_MMA);
    cudaFuncSetAttribute(k5, cudaFuncAttributeMaxDynamicSharedMemorySize, SMEM_MMA);
    cudaFuncSetAttribute(k6, cudaFuncAttributeMaxDynamicSharedMemorySize, SMEM_MMA);

    // 0: weight prep
    prepw<<<(4574592 + 255) / 256, 256>>>(a[0], bt[0], a[1], bt[1], a[2], bt[2],
                                          a[3], bt[3], a[4], bt[4], a[5], bt[5]);
    // 1: L1 SIMT -> planes p1
    conv1<<<dim3(16, 4, 128), 128>>>(x, cb[0], p1);
    // 2: L2 128->128, 32->16, s2: 65536 px -> 512 tiles, COUT=128 -> 1 co-block
    k2<<<dim3(512, 1), 256, SMEM_MMA>>>(w2q, p1, cb[1], p2, nullptr, nullptr);
    // 3: L3 128->256, 16x16: 512 tiles x 2 co-blocks
    k3<<<dim3(512, 2), 256, SMEM_MMA>>>(w3q, p2, cb[2], p3, nullptr, nullptr);
    // 4: L4 256->256, 16->8, s2: 128 tiles x 2 co-blocks
    k4<<<dim3(128, 2), 256, SMEM_MMA>>>(w4q, p3, cb[3], p4, nullptr, nullptr);
    // 5: L5 256->512, 8x8: 128 tiles x 4 co-blocks  <- ncu -s 5 target
    k5<<<dim3(128, 4), 256, SMEM_MMA>>>(w5q, p4, cb[4], p5, nullptr, nullptr);
    // 6: L6 512->512, 8->4, s2, sampled: 32 tiles x 4 co-blocks
    k6<<<dim3(32, 4), 256, SMEM_MMA>>>(w6q, p5, cb[5], nullptr, z6, noise);

    bn_stats<<<512, 256>>>(z6, gamma, beta, scale, shift);
    bn_norm<<<(2097152 + 255) / 256, 256>>>(z6, scale, shift, zbn);
    fc1_kernel<<<dim3(16, 4), 256>>>(zbn, fc1w, fc1b, fc1o);
    fc2_kernel<<<(2560 + 127) / 128, 128>>>(fc1o, fc2w, fc2b, (float*)d_out);
}

// round 13
// speedup vs baseline: 1.0013x; 1.0013x over previous
#include <cuda_runtime.h>
#include <cuda_fp16.h>
#include <math.h>
#include <stdint.h>

#define EPS 1e-5f

// ================= device scratch (no runtime allocation allowed) ==============
__device__ float g_wm1[3456], g_wv1[3456];

// weight variants, K-major [3][COUT*9*CIN] fp16 : 0=m_hi 1=m_lo 2=v
__device__ __half g_w2q[442368];
__device__ __half g_w3q[884736];
__device__ __half g_w4q[1769472];
__device__ __half g_w5q[3538944];
__device__ __half g_w6q[7077888];

// activation NHWC fp16 planes: [3][N*H*W*C] : 0=x_hi 1=x_lo 2=s
__device__ __half g_p1[100663296];  // (256,32,32,128)
__device__ __half g_p2[25165824];   // (256,16,16,128)
__device__ __half g_p3[50331648];   // (256,16,16,256)
__device__ __half g_p4[12582912];   // (256,8,8,256)
__device__ __half g_p5[25165824];   // (256,8,8,512)

__device__ float g_z6[2097152];   // [256,512,4,4] fp32 NCHW
__device__ float g_zbn[2097152];
__device__ float g_fc1o[262144];
__device__ float g_bnscale[512], g_bnshift[512];

// ================= packed f32x2 helpers (SIMT L1) ==============================
__device__ __forceinline__ unsigned long long bcast2(float x) {
    unsigned long long r; unsigned u = __float_as_uint(x);
    asm("mov.b64 %0, {%1, %1};" : "=l"(r) : "r"(u));
    return r;
}
__device__ __forceinline__ unsigned long long mul2(unsigned long long a, unsigned long long b) {
    unsigned long long d;
    asm("mul.rn.f32x2 %0, %1, %2;" : "=l"(d) : "l"(a), "l"(b));
    return d;
}
__device__ __forceinline__ void fma2(unsigned long long& d, unsigned long long a, unsigned long long b) {
    asm("fma.rn.f32x2 %0, %1, %2, %0;" : "+l"(d) : "l"(a), "l"(b));
}
__device__ __forceinline__ void unpack2(unsigned long long v, float& lo, float& hi) {
    unsigned ulo, uhi;
    asm("mov.b64 {%0, %1}, %2;" : "=r"(ulo), "=r"(uhi) : "l"(v));
    lo = __uint_as_float(ulo); hi = __uint_as_float(uhi);
}

// fp16 pair pack: low half = first element
__device__ __forceinline__ uint32_t pkh2(float a, float b) {
    uint32_t lo = (uint32_t)__half_as_ushort(__float2half_rn(a));
    uint32_t hi = (uint32_t)__half_as_ushort(__float2half_rn(b));
    return lo | (hi << 16);
}

// mma.sync m16n8k16 fp16 -> f32
#define MMA16816(C, A, B) asm volatile( \
    "mma.sync.aligned.m16n8k16.row.col.f32.f16.f16.f32 " \
    "{%0,%1,%2,%3},{%4,%5,%6,%7},{%8,%9},{%0,%1,%2,%3};" \
    : "+f"((C)[0]), "+f"((C)[1]), "+f"((C)[2]), "+f"((C)[3]) \
    : "r"((A)[0]), "r"((A)[1]), "r"((A)[2]), "r"((A)[3]), \
      "r"((B)[0]), "r"((B)[1]))

#define LDMX4(R, ADDR) asm volatile( \
    "ldmatrix.sync.aligned.m8n8.x4.shared.b16 {%0,%1,%2,%3}, [%4];" \
    : "=r"((R)[0]), "=r"((R)[1]), "=r"((R)[2]), "=r"((R)[3]) : "r"(ADDR))

// 16B async copy, global -> shared, L1-bypass; sz=0 zero-fills
__device__ __forceinline__ void cpa16(uint32_t dst, const void* src, int sz) {
    asm volatile("cp.async.cg.shared.global [%0], [%1], 16, %2;"
                 :: "r"(dst), "l"(src), "r"(sz));
}
__device__ __forceinline__ void cpa_commit() {
    asm volatile("cp.async.commit_group;" ::: "memory");
}
__device__ __forceinline__ void cpa_wait1() {
    asm volatile("cp.async.wait_group 1;" ::: "memory");
}
__device__ __forceinline__ void cpa_wait0() {
    asm volatile("cp.async.wait_group 0;" ::: "memory");
}

// ================= weight preprocessing (one launch) ===========================
__global__ void prepw(const float* __restrict__ a1, const float* __restrict__ b1,
                      const float* __restrict__ a2, const float* __restrict__ b2,
                      const float* __restrict__ a3, const float* __restrict__ b3,
                      const float* __restrict__ a4, const float* __restrict__ b4,
                      const float* __restrict__ a5, const float* __restrict__ b5,
                      const float* __restrict__ a6, const float* __restrict__ b6)
{
    int i = blockIdx.x * blockDim.x + threadIdx.x;
    if (i >= 4574592) return;

    const float *A, *Bp; int j, cin; __half* WQ; int wplane; bool l1 = false;
    if (i < 150912) {
        if (i < 3456) { A = a1; Bp = b1; j = i; l1 = true; cin = 3; WQ = nullptr; wplane = 0; }
        else          { A = a2; Bp = b2; j = i - 3456;   cin = 128; WQ = g_w2q; wplane = 147456; }
    } else if (i < 1035648) {
        if (i < 445824) { A = a3; Bp = b3; j = i - 150912; cin = 128; WQ = g_w3q; wplane = 294912; }
        else            { A = a4; Bp = b4; j = i - 445824; cin = 256; WQ = g_w4q; wplane = 589824; }
    } else {
        if (i < 2215296) { A = a5; Bp = b5; j = i - 1035648; cin = 256; WQ = g_w5q; wplane = 1179648; }
        else             { A = a6; Bp = b6; j = i - 2215296; cin = 512; WQ = g_w6q; wplane = 2359296; }
    }
    float p0 = 1.f / (1.f + expf(-A[j]));
    float sb = 1.f / (1.f + expf(-Bp[j]));
    float p1 = (1.f - p0) * sb;
    float m  = 2.f * p1 + p0 - 1.f;
    float v  = (1.f - p0) - m * m;
    if (l1) { g_wm1[j] = m; g_wv1[j] = v; return; }
    int k9 = cin * 9;
    int co  = j / k9;
    int r   = j - co * k9;
    int ci  = r / 9;
    int tap = r - ci * 9;
    int o   = co * k9 + tap * cin + ci;
    __half mh = __float2half_rn(m);
    WQ[o]              = mh;
    WQ[wplane + o]     = __float2half_rn(m - __half2float(mh));
    WQ[2 * wplane + o] = __float2half_rn(v);
}

// ================= L1 conv (SIMT, CIN=3) -> NHWC fp16 planes ===================
__global__ void __launch_bounds__(128)
conv1(const float* __restrict__ in, const float* __restrict__ bias,
      __half* __restrict__ pout)
{
    constexpr int CIN = 3, HIN = 32, WIN = 32, CK = 3;
    constexpr int TCO = 32, IPH = 10, IPW = 12;
    constexpr int XS_N = 2 * CK * IPH * IPW;
    constexpr int WS_N = CK * 9 * TCO;
    constexpr int NXV = 10, NF4 = 3, CP = 2, PX_T = 8;
    constexpr int OPLANE = 256 * 32 * 32 * 128;

    __shared__ __align__(16) float xs[XS_N];
    __shared__ __align__(16) float wsm[WS_N];
    __shared__ __align__(16) float wsv[WS_N];

    const int tid = threadIdx.x;
    const int tileX = blockIdx.x % 4, tileY = blockIdx.x / 4;
    const int coBase = blockIdx.y * TCO;
    const int nBase  = blockIdx.z * 2;
    const int oy0 = tileY * 8, ox0 = tileX * 8;

    const int co0 = (tid % 8) * 4;
    const int pg  = tid / 8;
    const int img = pg / 8;
    const int py  = pg % 8;

    unsigned long long aM[CP][PX_T], aV[CP][PX_T];
    #pragma unroll
    for (int p = 0; p < CP; p++)
        #pragma unroll
        for (int i = 0; i < PX_T; i++) { aM[p][i] = 0ull; aV[p][i] = 0ull; }

    for (int idx = tid; idx < XS_N; idx += 128) {
        int im = idx / (CK * IPH * IPW);
        int r  = idx - im * (CK * IPH * IPW);
        int ck = r / (IPH * IPW);
        int r2 = r - ck * (IPH * IPW);
        int iy = r2 / IPW;
        int ix = r2 - iy * IPW;
        int gy = oy0 - 1 + iy, gx = ox0 - 1 + ix;
        float v = 0.f;
        if (gy >= 0 && gy < HIN && gx >= 0 && gx < WIN)
            v = in[(((nBase + im) * CIN + ck) * HIN + gy) * WIN + gx];
        xs[idx] = v;
    }
    for (int idx = tid; idx < WS_N; idx += 128) {
        int ck  = idx / (9 * TCO);
        int rm  = idx - ck * (9 * TCO);
        int tap = rm / TCO;
        int co  = rm - tap * TCO;
        int g = ((coBase + co) * CIN + ck) * 9 + tap;
        wsm[idx] = g_wm1[g];
        wsv[idx] = g_wv1[g];
    }
    __syncthreads();

    #pragma unroll 1
    for (int ck = 0; ck < CK; ck++) {
        #pragma unroll
        for (int ky = 0; ky < 3; ky++) {
            const float* xrow = &xs[((img * CK + ck) * IPH + (py + ky)) * IPW];
            float4 f4[NF4];
            #pragma unroll
            for (int j = 0; j < NF4; j++)
                f4[j] = reinterpret_cast<const float4*>(xrow)[j];
            const float* xv = reinterpret_cast<const float*>(f4);
            unsigned long long xp[NXV], xxp[NXV];
            #pragma unroll
            for (int j = 0; j < NXV; j++) {
                xp[j]  = bcast2(xv[j]);
                xxp[j] = mul2(xp[j], xp[j]);
            }
            #pragma unroll
            for (int kx = 0; kx < 3; kx++) {
                const int tap = ky * 3 + kx;
                ulonglong2 m2 = *reinterpret_cast<const ulonglong2*>(&wsm[(ck * 9 + tap) * TCO + co0]);
                ulonglong2 v2 = *reinterpret_cast<const ulonglong2*>(&wsv[(ck * 9 + tap) * TCO + co0]);
                #pragma unroll
                for (int i = 0; i < PX_T; i++) {
                    fma2(aM[0][i], m2.x, xp[kx + i]);
                    fma2(aM[1][i], m2.y, xp[kx + i]);
                    fma2(aV[0][i], v2.x, xxp[kx + i]);
                    fma2(aV[1][i], v2.y, xxp[kx + i]);
                }
            }
        }
    }

    const int n = nBase + img;
    const int oy = oy0 + py;
    #pragma unroll
    for (int p = 0; p < CP; p++) {
        const int cA = coBase + co0 + 2 * p;
        const float bA = bias[cA], bB = bias[cA + 1];
        #pragma unroll
        for (int i = 0; i < PX_T; i++) {
            float mA, mB, vA, vB;
            unpack2(aM[p][i], mA, mB);
            unpack2(aV[p][i], vA, vB);
            mA += bA; mB += bB;
            float hA = erff(mA * rsqrtf(2.f * (vA + EPS)));
            float hB = erff(mB * rsqrtf(2.f * (vB + EPS)));
            int oi = ((n * 32 + oy) * 32 + (ox0 + i)) * 128 + cA;
            float lA = hA - __half2float(__float2half_rn(hA));
            float lB = hB - __half2float(__float2half_rn(hB));
            *(uint32_t*)&pout[oi]              = pkh2(hA, hB);
            *(uint32_t*)&pout[OPLANE + oi]     = pkh2(lA, lB);
            *(uint32_t*)&pout[2 * OPLANE + oi] = pkh2(hA * hA, hB * hB);
        }
    }
}

// ================= mma.sync conv layers 2-6 (v5: 512 thr, warp 32x32) ==========
// Block: 128px x 128co, 16 warps (512 thr), warp = 32px x 32co (mt=2, nt=4).
// Double-buffered cp.async pipeline. 4 warps/SMSP to hide latency chains.
// m = x_hi*wm_hi + x_lo*wm_hi + x_hi*wm_lo ; v = s*wv
template<int CIN, int COUT, int HIN, int WIN, int S, bool LAST>
__global__ void __launch_bounds__(512, 1)
conv_mma(const __half* __restrict__ wq,    // [3][COUT*9CIN]
         const __half* __restrict__ pin,   // [3 planes][256*HIN*WIN*CIN]
         const float* __restrict__ bias,
         __half* __restrict__ pout,        // planes (if !LAST)
         float* __restrict__ zout,         // NCHW fp32 (if LAST)
         const float* __restrict__ noise)
{
    constexpr int HO = HIN / S, WO = WIN / S;
    constexpr int PIX = HO * WO;
    constexpr int CG = CIN / 64;
    constexpr int NS = 9 * CG;
    constexpr int K9 = 9 * CIN;
    constexpr int WPLANE = COUT * K9;
    constexpr int IPLANE = 256 * HIN * WIN * CIN;
    constexpr int OPLANE = 256 * HO * WO * COUT;
    constexpr int AST = 72;                  // padded row stride (144 B)
    constexpr int APL = 128 * AST;           // A plane: 128 pixel rows
    constexpr int BPL = 128 * AST;           // B plane: 128 cout rows
    constexpr uint32_t BUF = (uint32_t)(3 * APL + 3 * BPL) * 2;  // 110592 B / stage

    extern __shared__ __align__(16) __half sm[];

    const int tid = threadIdx.x;
    const int wid = tid >> 5, lid = tid & 31;
    const int g = lid >> 2, t = lid & 3;
    const int wpx = wid >> 2, wco = wid & 3;     // 4 px-quarters x 4 co-quarters
    const int pixBase = blockIdx.x * 128;
    const int coBase  = blockIdx.y * 128;

    const uint32_t smb = (uint32_t)__cvta_generic_to_shared(sm);
    const int arow = (lid & 7) + ((lid >> 3) & 1) * 8;
    const int achk = ((lid >> 4) & 1) * 8;
    const int brow = (lid & 7) + ((lid >> 4) & 1) * 8;
    const int bchk = ((lid >> 3) & 1) * 8;
    const uint32_t aAddr0 = smb + (uint32_t)(((wpx * 32 + arow) * AST + achk) * 2);
    const uint32_t bAddr0 = smb + (uint32_t)(3 * APL * 2) +
                            (uint32_t)(((wco * 32 + brow) * AST + bchk) * 2);

    // staging: 3 A planes x 128 rows + 3 B variants x 128 rows = 768 row jobs
    auto stage = [&](int s, uint32_t bofs) {
        const int tap = s / CG, cg = s - tap * CG;
        const int ky = tap / 3, kx = tap - ky * 3;
        const int c0 = cg * 64;
        #pragma unroll 1
        for (int j = tid; j < 768; j += 512) {
            if (j < 384) {
                const int pl = j >> 7, row = j & 127;
                const int gp = pixBase + row;
                const int n  = gp / PIX;
                const int r  = gp - n * PIX;
                const int oy = r / WO, ox = r - (r / WO) * WO;
                const int iy = oy * S - 1 + ky, ix = ox * S - 1 + kx;
                uint32_t dst = smb + bofs + (uint32_t)((pl * APL + row * AST) * 2);
                const bool ok = (iy >= 0 && iy < HIN && ix >= 0 && ix < WIN);
                const __half* src = ok
                    ? pin + (size_t)pl * IPLANE + ((size_t)(n * HIN + iy) * WIN + ix) * CIN + c0
                    : pin;
                const int sz = ok ? 16 : 0;
                #pragma unroll
                for (int q = 0; q < 8; q++)
                    cpa16(dst + q * 16, src + q * 8, sz);
            } else {
                const int jj = j - 384;
                const int var = jj >> 7, row = jj & 127;
                const __half* src = wq + (size_t)var * WPLANE +
                                    (size_t)(coBase + row) * K9 + tap * CIN + c0;
                uint32_t dst = smb + bofs + (uint32_t)((3 * APL + var * BPL + row * AST) * 2);
                #pragma unroll
                for (int q = 0; q < 8; q++)
                    cpa16(dst + q * 16, src + q * 8, 16);
            }
        }
    };

    float accM[2][4][4], accV[2][4][4];
    #pragma unroll
    for (int mt = 0; mt < 2; mt++)
        #pragma unroll
        for (int nt = 0; nt < 4; nt++)
            #pragma unroll
            for (int e = 0; e < 4; e++) { accM[mt][nt][e] = 0.f; accV[mt][nt][e] = 0.f; }

    stage(0, 0);
    cpa_commit();

    #pragma unroll 1
    for (int s = 0; s < NS; s++) {
        if (s + 1 < NS) {
            stage(s + 1, (uint32_t)((s + 1) & 1) * BUF);
            cpa_commit();
            cpa_wait1();
        } else {
            cpa_wait0();
        }
        __syncthreads();

        const uint32_t bofs = (uint32_t)(s & 1) * BUF;
        #pragma unroll
        for (int ks = 0; ks < 4; ks++) {
            const uint32_t ksb = (uint32_t)(ks * 32) + bofs;
            uint32_t bmh[2][4], bml[2][4], bv_[2][4];
            #pragma unroll
            for (int ntp = 0; ntp < 2; ntp++) {
                const uint32_t b0 = bAddr0 + (uint32_t)(ntp * 16 * AST * 2) + ksb;
                LDMX4(bmh[ntp], b0);
                LDMX4(bml[ntp], b0 + (uint32_t)(BPL * 2));
                LDMX4(bv_[ntp], b0 + (uint32_t)(2 * BPL * 2));
            }
            uint32_t axh[2][4], axl[2][4], as_[2][4];
            #pragma unroll
            for (int mt = 0; mt < 2; mt++) {
                const uint32_t a0 = aAddr0 + (uint32_t)(mt * 16 * AST * 2) + ksb;
                LDMX4(axh[mt], a0);
                LDMX4(axl[mt], a0 + (uint32_t)(APL * 2));
                LDMX4(as_[mt], a0 + (uint32_t)(2 * APL * 2));
            }
            #pragma unroll
            for (int mt = 0; mt < 2; mt++)
                #pragma unroll
                for (int nt = 0; nt < 4; nt++) {
                    const int ntp = nt >> 1, o = (nt & 1) * 2;
                    MMA16816(accM[mt][nt], axh[mt], &bmh[ntp][o]);
                    MMA16816(accM[mt][nt], axl[mt], &bmh[ntp][o]);
                    MMA16816(accM[mt][nt], axh[mt], &bml[ntp][o]);
                    MMA16816(accV[mt][nt], as_[mt], &bv_[ntp][o]);
                }
        }
        __syncthreads();
    }

    // ---- epilogue ----
    #pragma unroll
    for (int mt = 0; mt < 2; mt++)
        #pragma unroll
        for (int nt = 0; nt < 4; nt++) {
            const int co0 = coBase + wco * 32 + nt * 8 + 2 * t;
            const float b0 = bias[co0], b1 = bias[co0 + 1];
            #pragma unroll
            for (int h2 = 0; h2 < 2; h2++) {
                const int gp = pixBase + wpx * 32 + mt * 16 + g + h2 * 8;
                float m0 = accM[mt][nt][2 * h2]     + b0;
                float m1 = accM[mt][nt][2 * h2 + 1] + b1;
                float v0 = accV[mt][nt][2 * h2];
                float v1 = accV[mt][nt][2 * h2 + 1];
                const int n = gp / PIX;
                const int r = gp - n * PIX;
                const int oy = r / WO, ox = r - (r / WO) * WO;
                if (LAST) {
                    int o0 = ((n * COUT + co0) * HO + oy) * WO + ox;
                    int o1 = o0 + HO * WO;
                    zout[o0] = m0 + sqrtf(v0 + EPS) * noise[o0];
                    zout[o1] = m1 + sqrtf(v1 + EPS) * noise[o1];
                } else {
                    float h0 = erff(m0 * rsqrtf(2.f * (v0 + EPS)));
                    float h1 = erff(m1 * rsqrtf(2.f * (v1 + EPS)));
                    float l0 = h0 - __half2float(__float2half_rn(h0));
                    float l1 = h1 - __half2float(__float2half_rn(h1));
                    int oi = ((n * HO + oy) * WO + ox) * COUT + co0;
                    *(uint32_t*)&pout[oi]              = pkh2(h0, h1);
                    *(uint32_t*)&pout[OPLANE + oi]     = pkh2(l0, l1);
                    *(uint32_t*)&pout[2 * OPLANE + oi] = pkh2(h0 * h0, h1 * h1);
                }
            }
        }
}

// ================= batchnorm / FC ==============================================
__global__ void bn_stats(const float* __restrict__ z, const float* __restrict__ gamma,
                         const float* __restrict__ beta, float* __restrict__ scale,
                         float* __restrict__ shift)
{
    __shared__ double ssum[256], ssq[256];
    int c = blockIdx.x, t = threadIdx.x;
    double s = 0.0, s2 = 0.0;
    for (int i = t; i < 4096; i += 256) {
        int n = i >> 4, qq = i & 15;
        float v = z[(n * 512 + c) * 16 + qq];
        s += v; s2 += (double)v * v;
    }
    ssum[t] = s; ssq[t] = s2;
    __syncthreads();
    for (int off = 128; off > 0; off >>= 1) {
        if (t < off) { ssum[t] += ssum[t + off]; ssq[t] += ssq[t + off]; }
        __syncthreads();
    }
    if (t == 0) {
        double mean = ssum[0] / 4096.0;
        double var  = ssq[0] / 4096.0 - mean * mean;
        float sc = gamma[c] * rsqrtf((float)var + EPS);
        scale[c] = sc;
        shift[c] = beta[c] - (float)mean * sc;
    }
}

__global__ void bn_norm(const float* __restrict__ z, const float* __restrict__ scale,
                        const float* __restrict__ shift, float* __restrict__ out)
{
    int idx = blockIdx.x * blockDim.x + threadIdx.x;
    if (idx < 256 * 8192) {
        int c = (idx >> 4) & 511;
        float v = z[idx] * scale[c] + shift[c];
        out[idx] = v > 0.f ? v : 0.f;
    }
}

__global__ void __launch_bounds__(256)
fc1_kernel(const float* __restrict__ A, const float* __restrict__ W,
           const float* __restrict__ bias, float* __restrict__ C)
{
    __shared__ float As[64][33];
    __shared__ float Ws[64][33];
    const int t = threadIdx.x;
    const int mBlk = blockIdx.y * 64, nBlk = blockIdx.x * 64;
    const int msub = (t % 16) * 4, nsub = (t / 16) * 4;
    float acc[4][4];
    #pragma unroll
    for (int i = 0; i < 4; i++)
        #pragma unroll
        for (int j = 0; j < 4; j++) acc[i][j] = 0.f;

    for (int k0 = 0; k0 < 8192; k0 += 32) {
        for (int i = t; i < 64 * 32; i += 256) {
            int r = i >> 5, kk = i & 31;
            As[r][kk] = A[(mBlk + r) * 8192 + k0 + kk];
            Ws[r][kk] = W[(nBlk + r) * 8192 + k0 + kk];
        }
        __syncthreads();
        #pragma unroll
        for (int kk = 0; kk < 32; kk++) {
            float a0 = As[msub][kk], a1 = As[msub + 1][kk], a2 = As[msub + 2][kk], a3 = As[msub + 3][kk];
            float w0 = Ws[nsub][kk], w1 = Ws[nsub + 1][kk], w2 = Ws[nsub + 2][kk], w3 = Ws[nsub + 3][kk];
            acc[0][0] += a0 * w0; acc[0][1] += a0 * w1; acc[0][2] += a0 * w2; acc[0][3] += a0 * w3;
            acc[1][0] += a1 * w0; acc[1][1] += a1 * w1; acc[1][2] += a1 * w2; acc[1][3] += a1 * w3;
            acc[2][0] += a2 * w0; acc[2][1] += a2 * w1; acc[2][2] += a2 * w2; acc[2][3] += a2 * w3;
            acc[3][0] += a3 * w0; acc[3][1] += a3 * w1; acc[3][2] += a3 * w2; acc[3][3] += a3 * w3;
        }
        __syncthreads();
    }
    #pragma unroll
    for (int i = 0; i < 4; i++)
        #pragma unroll
        for (int j = 0; j < 4; j++) {
            float v = acc[i][j] + bias[nBlk + nsub + j];
            C[(mBlk + msub + i) * 1024 + nBlk + nsub + j] = v > 0.f ? v : 0.f;
        }
}

__global__ void fc2_kernel(const float* __restrict__ A, const float* __restrict__ W,
                           const float* __restrict__ bias, float* __restrict__ out)
{
    int idx = blockIdx.x * blockDim.x + threadIdx.x;
    if (idx >= 2560) return;
    int n = idx / 10, j = idx - n * 10;
    const float* a = A + n * 1024;
    const float* w = W + j * 1024;
    float s = bias[j];
    for (int k = 0; k < 1024; k += 4)
        s += a[k] * w[k] + a[k + 1] * w[k + 1] + a[k + 2] * w[k + 2] + a[k + 3] * w[k + 3];
    out[idx] = s;
}

// ================= launch ======================================================
extern "C" void kernel_launch(void* const* d_in, const int* in_sizes, int n_in,
                              void* d_out, int out_size)
{
    (void)in_sizes; (void)n_in; (void)out_size;
    const float* x = (const float*)d_in[0];
    const float* a[6]  = {(const float*)d_in[1],  (const float*)d_in[4],  (const float*)d_in[7],
                          (const float*)d_in[10], (const float*)d_in[13], (const float*)d_in[16]};
    const float* bt[6] = {(const float*)d_in[2],  (const float*)d_in[5],  (const float*)d_in[8],
                          (const float*)d_in[11], (const float*)d_in[14], (const float*)d_in[17]};
    const float* cb[6] = {(const float*)d_in[3],  (const float*)d_in[6],  (const float*)d_in[9],
                          (const float*)d_in[12], (const float*)d_in[15], (const float*)d_in[18]};
    const float* gamma = (const float*)d_in[19];
    const float* beta  = (const float*)d_in[20];
    const float* fc1w  = (const float*)d_in[21];
    const float* fc1b  = (const float*)d_in[22];
    const float* fc2w  = (const float*)d_in[23];
    const float* fc2b  = (const float*)d_in[24];
    const float* noise = (const float*)d_in[25];

    __half *w2q, *w3q, *w4q, *w5q, *w6q, *p1, *p2, *p3, *p4, *p5;
    cudaGetSymbolAddress((void**)&w2q, g_w2q);
    cudaGetSymbolAddress((void**)&w3q, g_w3q);
    cudaGetSymbolAddress((void**)&w4q, g_w4q);
    cudaGetSymbolAddress((void**)&w5q, g_w5q);
    cudaGetSymbolAddress((void**)&w6q, g_w6q);
    cudaGetSymbolAddress((void**)&p1, g_p1);
    cudaGetSymbolAddress((void**)&p2, g_p2);
    cudaGetSymbolAddress((void**)&p3, g_p3);
    cudaGetSymbolAddress((void**)&p4, g_p4);
    cudaGetSymbolAddress((void**)&p5, g_p5);

    float *z6, *zbn, *fc1o, *scale, *shift;
    cudaGetSymbolAddress((void**)&z6,  g_z6);
    cudaGetSymbolAddress((void**)&zbn, g_zbn);
    cudaGetSymbolAddress((void**)&fc1o, g_fc1o);
    cudaGetSymbolAddress((void**)&scale, g_bnscale);
    cudaGetSymbolAddress((void**)&shift, g_bnshift);

    constexpr int SMEM_MMA = 2 * (3 * 128 + 3 * 128) * 72 * 2;   // 221184 B
    auto k2 = conv_mma<128, 128, 32, 32, 2, false>;
    auto k3 = conv_mma<128, 256, 16, 16, 1, false>;
    auto k4 = conv_mma<256, 256, 16, 16, 2, false>;
    auto k5 = conv_mma<256, 512, 8,  8,  1, false>;
    auto k6 = conv_mma<512, 512, 8,  8,  2, true>;
    cudaFuncSetAttribute(k2, cudaFuncAttributeMaxDynamicSharedMemorySize, SMEM_MMA);
    cudaFuncSetAttribute(k3, cudaFuncAttributeMaxDynamicSharedMemorySize, SMEM_MMA);
    cudaFuncSetAttribute(k4, cudaFuncAttributeMaxDynamicSharedMemorySize, SMEM_MMA);
    cudaFuncSetAttribute(k5, cudaFuncAttributeMaxDynamicSharedMemorySize, SMEM_MMA);
    cudaFuncSetAttribute(k6, cudaFuncAttributeMaxDynamicSharedMemorySize, SMEM_MMA);

    // 0: weight prep
    prepw<<<(4574592 + 255) / 256, 256>>>(a[0], bt[0], a[1], bt[1], a[2], bt[2],
                                          a[3], bt[3], a[4], bt[4], a[5], bt[5]);
    // 1: L1 SIMT -> planes p1
    conv1<<<dim3(16, 4, 128), 128>>>(x, cb[0], p1);
    // 2: L2 128->128, 32->16, s2: 65536 px -> 512 tiles, COUT=128 -> 1 co-block
    k2<<<dim3(512, 1), 512, SMEM_MMA>>>(w2q, p1, cb[1], p2, nullptr, nullptr);
    // 3: L3 128->256, 16x16: 512 tiles x 2 co-blocks
    k3<<<dim3(512, 2), 512, SMEM_MMA>>>(w3q, p2, cb[2], p3, nullptr, nullptr);
    // 4: L4 256->256, 16->8, s2: 128 tiles x 2 co-blocks
    k4<<<dim3(128, 2), 512, SMEM_MMA>>>(w4q, p3, cb[3], p4, nullptr, nullptr);
    // 5: L5 256->512, 8x8: 128 tiles x 4 co-blocks  <- ncu -s 5 target
    k5<<<dim3(128, 4), 512, SMEM_MMA>>>(w5q, p4, cb[4], p5, nullptr, nullptr);
    // 6: L6 512->512, 8->4, s2, sampled: 32 tiles x 4 co-blocks
    k6<<<dim3(32, 4), 512, SMEM_MMA>>>(w6q, p5, cb[5], nullptr, z6, noise);

    bn_stats<<<512, 256>>>(z6, gamma, beta, scale, shift);
    bn_norm<<<(2097152 + 255) / 256, 256>>>(z6, scale, shift, zbn);
    fc1_kernel<<<dim3(16, 4), 256>>>(zbn, fc1w, fc1b, fc1o);
    fc2_kernel<<<(2560 + 127) / 128, 128>>>(fc1o, fc2w, fc2b, (float*)d_out);
}

// round 14
// speedup vs baseline: 1.2956x; 1.2940x over previous
#include <cuda_runtime.h>
#include <cuda_fp16.h>
#include <math.h>
#include <stdint.h>

#define EPS 1e-5f

// ================= device scratch (no runtime allocation allowed) ==============
__device__ float g_wm1[3456], g_wv1[3456];

// weight variants, K-major [2][COUT*9*CIN] fp16 : 0=wm(rn) 1=wv
__device__ __half g_w2q[294912];
__device__ __half g_w3q[589824];
__device__ __half g_w4q[1179648];
__device__ __half g_w5q[2359296];
__device__ __half g_w6q[4718592];

// activation NHWC fp16 planes: [3][N*H*W*C] : 0=x_hi 1=x_lo 2=s
__device__ __half g_p1[100663296];  // (256,32,32,128)
__device__ __half g_p2[25165824];   // (256,16,16,128)
__device__ __half g_p3[50331648];   // (256,16,16,256)
__device__ __half g_p4[12582912];   // (256,8,8,256)
__device__ __half g_p5[25165824];   // (256,8,8,512)

__device__ float g_z6[2097152];   // [256,512,4,4] fp32 NCHW
__device__ float g_zbn[2097152];
__device__ float g_fc1o[262144];
__device__ float g_bnscale[512], g_bnshift[512];

// ================= packed f32x2 helpers (SIMT L1) ==============================
__device__ __forceinline__ unsigned long long bcast2(float x) {
    unsigned long long r; unsigned u = __float_as_uint(x);
    asm("mov.b64 %0, {%1, %1};" : "=l"(r) : "r"(u));
    return r;
}
__device__ __forceinline__ unsigned long long mul2(unsigned long long a, unsigned long long b) {
    unsigned long long d;
    asm("mul.rn.f32x2 %0, %1, %2;" : "=l"(d) : "l"(a), "l"(b));
    return d;
}
__device__ __forceinline__ void fma2(unsigned long long& d, unsigned long long a, unsigned long long b) {
    asm("fma.rn.f32x2 %0, %1, %2, %0;" : "+l"(d) : "l"(a), "l"(b));
}
__device__ __forceinline__ void unpack2(unsigned long long v, float& lo, float& hi) {
    unsigned ulo, uhi;
    asm("mov.b64 {%0, %1}, %2;" : "=r"(ulo), "=r"(uhi) : "l"(v));
    lo = __uint_as_float(ulo); hi = __uint_as_float(uhi);
}

// fp16 pair pack: low half = first element
__device__ __forceinline__ uint32_t pkh2(float a, float b) {
    uint32_t lo = (uint32_t)__half_as_ushort(__float2half_rn(a));
    uint32_t hi = (uint32_t)__half_as_ushort(__float2half_rn(b));
    return lo | (hi << 16);
}

// mma.sync m16n8k16 fp16 -> f32
#define MMA16816(C, A, B) asm volatile( \
    "mma.sync.aligned.m16n8k16.row.col.f32.f16.f16.f32 " \
    "{%0,%1,%2,%3},{%4,%5,%6,%7},{%8,%9},{%0,%1,%2,%3};" \
    : "+f"((C)[0]), "+f"((C)[1]), "+f"((C)[2]), "+f"((C)[3]) \
    : "r"((A)[0]), "r"((A)[1]), "r"((A)[2]), "r"((A)[3]), \
      "r"((B)[0]), "r"((B)[1]))

#define LDMX4(R, ADDR) asm volatile( \
    "ldmatrix.sync.aligned.m8n8.x4.shared.b16 {%0,%1,%2,%3}, [%4];" \
    : "=r"((R)[0]), "=r"((R)[1]), "=r"((R)[2]), "=r"((R)[3]) : "r"(ADDR))

// 16B async copy, global -> shared, L1-bypass; sz=0 zero-fills
__device__ __forceinline__ void cpa16(uint32_t dst, const void* src, int sz) {
    asm volatile("cp.async.cg.shared.global [%0], [%1], 16, %2;"
                 :: "r"(dst), "l"(src), "r"(sz));
}
__device__ __forceinline__ void cpa_commit() {
    asm volatile("cp.async.commit_group;" ::: "memory");
}
__device__ __forceinline__ void cpa_wait0() {
    asm volatile("cp.async.wait_group 0;" ::: "memory");
}

// ================= weight preprocessing (one launch) ===========================
__global__ void prepw(const float* __restrict__ a1, const float* __restrict__ b1,
                      const float* __restrict__ a2, const float* __restrict__ b2,
                      const float* __restrict__ a3, const float* __restrict__ b3,
                      const float* __restrict__ a4, const float* __restrict__ b4,
                      const float* __restrict__ a5, const float* __restrict__ b5,
                      const float* __restrict__ a6, const float* __restrict__ b6)
{
    int i = blockIdx.x * blockDim.x + threadIdx.x;
    if (i >= 4574592) return;

    const float *A, *Bp; int j, cin; __half* WQ; int wplane; bool l1 = false;
    if (i < 150912) {
        if (i < 3456) { A = a1; Bp = b1; j = i; l1 = true; cin = 3; WQ = nullptr; wplane = 0; }
        else          { A = a2; Bp = b2; j = i - 3456;   cin = 128; WQ = g_w2q; wplane = 147456; }
    } else if (i < 1035648) {
        if (i < 445824) { A = a3; Bp = b3; j = i - 150912; cin = 128; WQ = g_w3q; wplane = 294912; }
        else            { A = a4; Bp = b4; j = i - 445824; cin = 256; WQ = g_w4q; wplane = 589824; }
    } else {
        if (i < 2215296) { A = a5; Bp = b5; j = i - 1035648; cin = 256; WQ = g_w5q; wplane = 1179648; }
        else             { A = a6; Bp = b6; j = i - 2215296; cin = 512; WQ = g_w6q; wplane = 2359296; }
    }
    float p0 = 1.f / (1.f + expf(-A[j]));
    float sb = 1.f / (1.f + expf(-Bp[j]));
    float p1 = (1.f - p0) * sb;
    float m  = 2.f * p1 + p0 - 1.f;
    float v  = (1.f - p0) - m * m;
    if (l1) { g_wm1[j] = m; g_wv1[j] = v; return; }
    int k9 = cin * 9;
    int co  = j / k9;
    int r   = j - co * k9;
    int ci  = r / 9;
    int tap = r - ci * 9;
    int o   = co * k9 + tap * cin + ci;
    WQ[o]          = __float2half_rn(m);
    WQ[wplane + o] = __float2half_rn(v);
}

// ================= L1 conv (SIMT, CIN=3) -> NHWC fp16 planes ===================
__global__ void __launch_bounds__(128)
conv1(const float* __restrict__ in, const float* __restrict__ bias,
      __half* __restrict__ pout)
{
    constexpr int CIN = 3, HIN = 32, WIN = 32, CK = 3;
    constexpr int TCO = 32, IPH = 10, IPW = 12;
    constexpr int XS_N = 2 * CK * IPH * IPW;
    constexpr int WS_N = CK * 9 * TCO;
    constexpr int NXV = 10, NF4 = 3, CP = 2, PX_T = 8;
    constexpr int OPLANE = 256 * 32 * 32 * 128;

    __shared__ __align__(16) float xs[XS_N];
    __shared__ __align__(16) float wsm[WS_N];
    __shared__ __align__(16) float wsv[WS_N];

    const int tid = threadIdx.x;
    const int tileX = blockIdx.x % 4, tileY = blockIdx.x / 4;
    const int coBase = blockIdx.y * TCO;
    const int nBase  = blockIdx.z * 2;
    const int oy0 = tileY * 8, ox0 = tileX * 8;

    const int co0 = (tid % 8) * 4;
    const int pg  = tid / 8;
    const int img = pg / 8;
    const int py  = pg % 8;

    unsigned long long aM[CP][PX_T], aV[CP][PX_T];
    #pragma unroll
    for (int p = 0; p < CP; p++)
        #pragma unroll
        for (int i = 0; i < PX_T; i++) { aM[p][i] = 0ull; aV[p][i] = 0ull; }

    for (int idx = tid; idx < XS_N; idx += 128) {
        int im = idx / (CK * IPH * IPW);
        int r  = idx - im * (CK * IPH * IPW);
        int ck = r / (IPH * IPW);
        int r2 = r - ck * (IPH * IPW);
        int iy = r2 / IPW;
        int ix = r2 - iy * IPW;
        int gy = oy0 - 1 + iy, gx = ox0 - 1 + ix;
        float v = 0.f;
        if (gy >= 0 && gy < HIN && gx >= 0 && gx < WIN)
            v = in[(((nBase + im) * CIN + ck) * HIN + gy) * WIN + gx];
        xs[idx] = v;
    }
    for (int idx = tid; idx < WS_N; idx += 128) {
        int ck  = idx / (9 * TCO);
        int rm  = idx - ck * (9 * TCO);
        int tap = rm / TCO;
        int co  = rm - tap * TCO;
        int g = ((coBase + co) * CIN + ck) * 9 + tap;
        wsm[idx] = g_wm1[g];
        wsv[idx] = g_wv1[g];
    }
    __syncthreads();

    #pragma unroll 1
    for (int ck = 0; ck < CK; ck++) {
        #pragma unroll
        for (int ky = 0; ky < 3; ky++) {
            const float* xrow = &xs[((img * CK + ck) * IPH + (py + ky)) * IPW];
            float4 f4[NF4];
            #pragma unroll
            for (int j = 0; j < NF4; j++)
                f4[j] = reinterpret_cast<const float4*>(xrow)[j];
            const float* xv = reinterpret_cast<const float*>(f4);
            unsigned long long xp[NXV], xxp[NXV];
            #pragma unroll
            for (int j = 0; j < NXV; j++) {
                xp[j]  = bcast2(xv[j]);
                xxp[j] = mul2(xp[j], xp[j]);
            }
            #pragma unroll
            for (int kx = 0; kx < 3; kx++) {
                const int tap = ky * 3 + kx;
                ulonglong2 m2 = *reinterpret_cast<const ulonglong2*>(&wsm[(ck * 9 + tap) * TCO + co0]);
                ulonglong2 v2 = *reinterpret_cast<const ulonglong2*>(&wsv[(ck * 9 + tap) * TCO + co0]);
                #pragma unroll
                for (int i = 0; i < PX_T; i++) {
                    fma2(aM[0][i], m2.x, xp[kx + i]);
                    fma2(aM[1][i], m2.y, xp[kx + i]);
                    fma2(aV[0][i], v2.x, xxp[kx + i]);
                    fma2(aV[1][i], v2.y, xxp[kx + i]);
                }
            }
        }
    }

    const int n = nBase + img;
    const int oy = oy0 + py;
    #pragma unroll
    for (int p = 0; p < CP; p++) {
        const int cA = coBase + co0 + 2 * p;
        const float bA = bias[cA], bB = bias[cA + 1];
        #pragma unroll
        for (int i = 0; i < PX_T; i++) {
            float mA, mB, vA, vB;
            unpack2(aM[p][i], mA, mB);
            unpack2(aV[p][i], vA, vB);
            mA += bA; mB += bB;
            float hA = erff(mA * rsqrtf(2.f * (vA + EPS)));
            float hB = erff(mB * rsqrtf(2.f * (vB + EPS)));
            int oi = ((n * 32 + oy) * 32 + (ox0 + i)) * 128 + cA;
            float lA = hA - __half2float(__float2half_rn(hA));
            float lB = hB - __half2float(__float2half_rn(hB));
            *(uint32_t*)&pout[oi]              = pkh2(hA, hB);
            *(uint32_t*)&pout[OPLANE + oi]     = pkh2(lA, lB);
            *(uint32_t*)&pout[2 * OPLANE + oi] = pkh2(hA * hA, hB * hB);
        }
    }
}

// ================= mma.sync conv layers 2-6 (v6: 3-product, overlapped stage) ==
// Block: 128px x 128co, 16 warps (512 thr), warp = 32px x 32co (mt=2, nt=4).
// m = (x_hi + x_lo) * wm_rn  (exact activation, weight-rounding error only)
// v = s * wv
// Staging for stage s+1 is issued between ks0 and ks1 of compute(s).
template<int CIN, int COUT, int HIN, int WIN, int S, bool LAST>
__global__ void __launch_bounds__(512, 1)
conv_mma(const __half* __restrict__ wq,    // [2][COUT*9CIN] : wm, wv
         const __half* __restrict__ pin,   // [3 planes][256*HIN*WIN*CIN]
         const float* __restrict__ bias,
         __half* __restrict__ pout,        // planes (if !LAST)
         float* __restrict__ zout,         // NCHW fp32 (if LAST)
         const float* __restrict__ noise)
{
    constexpr int HO = HIN / S, WO = WIN / S;
    constexpr int PIX = HO * WO;
    constexpr int CG = CIN / 64;
    constexpr int NS = 9 * CG;
    constexpr int K9 = 9 * CIN;
    constexpr int WPLANE = COUT * K9;
    constexpr int IPLANE = 256 * HIN * WIN * CIN;
    constexpr int OPLANE = 256 * HO * WO * COUT;
    constexpr int AST = 72;                  // padded row stride (144 B)
    constexpr int APL = 128 * AST;           // A plane: 128 pixel rows
    constexpr int BPL = 128 * AST;           // B plane: 128 cout rows
    constexpr uint32_t BUF = (uint32_t)(3 * APL + 2 * BPL) * 2;  // 92160 B / stage

    extern __shared__ __align__(16) __half sm[];

    const int tid = threadIdx.x;
    const int wid = tid >> 5, lid = tid & 31;
    const int g = lid >> 2, t = lid & 3;
    const int wpx = wid >> 2, wco = wid & 3;     // 4 px-quarters x 4 co-quarters
    const int pixBase = blockIdx.x * 128;
    const int coBase  = blockIdx.y * 128;

    const uint32_t smb = (uint32_t)__cvta_generic_to_shared(sm);
    const int arow = (lid & 7) + ((lid >> 3) & 1) * 8;
    const int achk = ((lid >> 4) & 1) * 8;
    const int brow = (lid & 7) + ((lid >> 4) & 1) * 8;
    const int bchk = ((lid >> 3) & 1) * 8;
    const uint32_t aAddr0 = smb + (uint32_t)(((wpx * 32 + arow) * AST + achk) * 2);
    const uint32_t bAddr0 = smb + (uint32_t)(3 * APL * 2) +
                            (uint32_t)(((wco * 32 + brow) * AST + bchk) * 2);

    // staging: 3 A planes x 128 rows + 2 B variants x 128 rows = 640 row jobs
    auto stage = [&](int s, uint32_t bofs) {
        const int tap = s / CG, cg = s - tap * CG;
        const int ky = tap / 3, kx = tap - ky * 3;
        const int c0 = cg * 64;
        #pragma unroll 1
        for (int j = tid; j < 640; j += 512) {
            if (j < 384) {
                const int pl = j >> 7, row = j & 127;
                const int gp = pixBase + row;
                const int n  = gp / PIX;
                const int r  = gp - n * PIX;
                const int oy = r / WO, ox = r - (r / WO) * WO;
                const int iy = oy * S - 1 + ky, ix = ox * S - 1 + kx;
                uint32_t dst = smb + bofs + (uint32_t)((pl * APL + row * AST) * 2);
                const bool ok = (iy >= 0 && iy < HIN && ix >= 0 && ix < WIN);
                const __half* src = ok
                    ? pin + (size_t)pl * IPLANE + ((size_t)(n * HIN + iy) * WIN + ix) * CIN + c0
                    : pin;
                const int sz = ok ? 16 : 0;
                #pragma unroll
                for (int q = 0; q < 8; q++)
                    cpa16(dst + q * 16, src + q * 8, sz);
            } else {
                const int jj = j - 384;
                const int var = jj >> 7, row = jj & 127;
                const __half* src = wq + (size_t)var * WPLANE +
                                    (size_t)(coBase + row) * K9 + tap * CIN + c0;
                uint32_t dst = smb + bofs + (uint32_t)((3 * APL + var * BPL + row * AST) * 2);
                #pragma unroll
                for (int q = 0; q < 8; q++)
                    cpa16(dst + q * 16, src + q * 8, 16);
            }
        }
    };

    float accM[2][4][4], accV[2][4][4];
    #pragma unroll
    for (int mt = 0; mt < 2; mt++)
        #pragma unroll
        for (int nt = 0; nt < 4; nt++)
            #pragma unroll
            for (int e = 0; e < 4; e++) { accM[mt][nt][e] = 0.f; accV[mt][nt][e] = 0.f; }

    // one k-step of compute on buffer bofs
    auto compute_ks = [&](int ks, uint32_t bofs) {
        const uint32_t ksb = (uint32_t)(ks * 32) + bofs;
        uint32_t bm[2][4], bv[2][4];
        #pragma unroll
        for (int ntp = 0; ntp < 2; ntp++) {
            const uint32_t b0 = bAddr0 + (uint32_t)(ntp * 16 * AST * 2) + ksb;
            LDMX4(bm[ntp], b0);
            LDMX4(bv[ntp], b0 + (uint32_t)(BPL * 2));
        }
        uint32_t axh[2][4], axl[2][4], as_[2][4];
        #pragma unroll
        for (int mt = 0; mt < 2; mt++) {
            const uint32_t a0 = aAddr0 + (uint32_t)(mt * 16 * AST * 2) + ksb;
            LDMX4(axh[mt], a0);
            LDMX4(axl[mt], a0 + (uint32_t)(APL * 2));
            LDMX4(as_[mt], a0 + (uint32_t)(2 * APL * 2));
        }
        #pragma unroll
        for (int mt = 0; mt < 2; mt++)
            #pragma unroll
            for (int nt = 0; nt < 4; nt++) {
                const int ntp = nt >> 1, o = (nt & 1) * 2;
                MMA16816(accM[mt][nt], axh[mt], &bm[ntp][o]);
                MMA16816(accM[mt][nt], axl[mt], &bm[ntp][o]);
                MMA16816(accV[mt][nt], as_[mt], &bv[ntp][o]);
            }
    };

    stage(0, 0);
    cpa_commit();

    #pragma unroll 1
    for (int s = 0; s < NS; s++) {
        cpa_wait0();          // buffer s ready (only group s pending)
        __syncthreads();
        const uint32_t bofs = (uint32_t)(s & 1) * BUF;

        compute_ks(0, bofs);
        if (s + 1 < NS) {     // overlap next-stage issue with remaining compute
            stage(s + 1, (uint32_t)((s + 1) & 1) * BUF);
            cpa_commit();
        }
        compute_ks(1, bofs);
        compute_ks(2, bofs);
        compute_ks(3, bofs);
        __syncthreads();      // all warps done with buffer s before it is restaged
    }

    // ---- epilogue ----
    #pragma unroll
    for (int mt = 0; mt < 2; mt++)
        #pragma unroll
        for (int nt = 0; nt < 4; nt++) {
            const int co0 = coBase + wco * 32 + nt * 8 + 2 * t;
            const float b0 = bias[co0], b1 = bias[co0 + 1];
            #pragma unroll
            for (int h2 = 0; h2 < 2; h2++) {
                const int gp = pixBase + wpx * 32 + mt * 16 + g + h2 * 8;
                float m0 = accM[mt][nt][2 * h2]     + b0;
                float m1 = accM[mt][nt][2 * h2 + 1] + b1;
                float v0 = accV[mt][nt][2 * h2];
                float v1 = accV[mt][nt][2 * h2 + 1];
                const int n = gp / PIX;
                const int r = gp - n * PIX;
                const int oy = r / WO, ox = r - (r / WO) * WO;
                if (LAST) {
                    int o0 = ((n * COUT + co0) * HO + oy) * WO + ox;
                    int o1 = o0 + HO * WO;
                    zout[o0] = m0 + sqrtf(v0 + EPS) * noise[o0];
                    zout[o1] = m1 + sqrtf(v1 + EPS) * noise[o1];
                } else {
                    float h0 = erff(m0 * rsqrtf(2.f * (v0 + EPS)));
                    float h1 = erff(m1 * rsqrtf(2.f * (v1 + EPS)));
                    float l0 = h0 - __half2float(__float2half_rn(h0));
                    float l1 = h1 - __half2float(__float2half_rn(h1));
                    int oi = ((n * HO + oy) * WO + ox) * COUT + co0;
                    *(uint32_t*)&pout[oi]              = pkh2(h0, h1);
                    *(uint32_t*)&pout[OPLANE + oi]     = pkh2(l0, l1);
                    *(uint32_t*)&pout[2 * OPLANE + oi] = pkh2(h0 * h0, h1 * h1);
                }
            }
        }
}

// ================= batchnorm / FC ==============================================
__global__ void bn_stats(const float* __restrict__ z, const float* __restrict__ gamma,
                         const float* __restrict__ beta, float* __restrict__ scale,
                         float* __restrict__ shift)
{
    __shared__ double ssum[256], ssq[256];
    int c = blockIdx.x, t = threadIdx.x;
    double s = 0.0, s2 = 0.0;
    for (int i = t; i < 4096; i += 256) {
        int n = i >> 4, qq = i & 15;
        float v = z[(n * 512 + c) * 16 + qq];
        s += v; s2 += (double)v * v;
    }
    ssum[t] = s; ssq[t] = s2;
    __syncthreads();
    for (int off = 128; off > 0; off >>= 1) {
        if (t < off) { ssum[t] += ssum[t + off]; ssq[t] += ssq[t + off]; }
        __syncthreads();
    }
    if (t == 0) {
        double mean = ssum[0] / 4096.0;
        double var  = ssq[0] / 4096.0 - mean * mean;
        float sc = gamma[c] * rsqrtf((float)var + EPS);
        scale[c] = sc;
        shift[c] = beta[c] - (float)mean * sc;
    }
}

__global__ void bn_norm(const float* __restrict__ z, const float* __restrict__ scale,
                        const float* __restrict__ shift, float* __restrict__ out)
{
    int idx = blockIdx.x * blockDim.x + threadIdx.x;
    if (idx < 256 * 8192) {
        int c = (idx >> 4) & 511;
        float v = z[idx] * scale[c] + shift[c];
        out[idx] = v > 0.f ? v : 0.f;
    }
}

__global__ void __launch_bounds__(256)
fc1_kernel(const float* __restrict__ A, const float* __restrict__ W,
           const float* __restrict__ bias, float* __restrict__ C)
{
    __shared__ float As[64][33];
    __shared__ float Ws[64][33];
    const int t = threadIdx.x;
    const int mBlk = blockIdx.y * 64, nBlk = blockIdx.x * 64;
    const int msub = (t % 16) * 4, nsub = (t / 16) * 4;
    float acc[4][4];
    #pragma unroll
    for (int i = 0; i < 4; i++)
        #pragma unroll
        for (int j = 0; j < 4; j++) acc[i][j] = 0.f;

    for (int k0 = 0; k0 < 8192; k0 += 32) {
        for (int i = t; i < 64 * 32; i += 256) {
            int r = i >> 5, kk = i & 31;
            As[r][kk] = A[(mBlk + r) * 8192 + k0 + kk];
            Ws[r][kk] = W[(nBlk + r) * 8192 + k0 + kk];
        }
        __syncthreads();
        #pragma unroll
        for (int kk = 0; kk < 32; kk++) {
            float a0 = As[msub][kk], a1 = As[msub + 1][kk], a2 = As[msub + 2][kk], a3 = As[msub + 3][kk];
            float w0 = Ws[nsub][kk], w1 = Ws[nsub + 1][kk], w2 = Ws[nsub + 2][kk], w3 = Ws[nsub + 3][kk];
            acc[0][0] += a0 * w0; acc[0][1] += a0 * w1; acc[0][2] += a0 * w2; acc[0][3] += a0 * w3;
            acc[1][0] += a1 * w0; acc[1][1] += a1 * w1; acc[1][2] += a1 * w2; acc[1][3] += a1 * w3;
            acc[2][0] += a2 * w0; acc[2][1] += a2 * w1; acc[2][2] += a2 * w2; acc[2][3] += a2 * w3;
            acc[3][0] += a3 * w0; acc[3][1] += a3 * w1; acc[3][2] += a3 * w2; acc[3][3] += a3 * w3;
        }
        __syncthreads();
    }
    #pragma unroll
    for (int i = 0; i < 4; i++)
        #pragma unroll
        for (int j = 0; j < 4; j++) {
            float v = acc[i][j] + bias[nBlk + nsub + j];
            C[(mBlk + msub + i) * 1024 + nBlk + nsub + j] = v > 0.f ? v : 0.f;
        }
}

__global__ void fc2_kernel(const float* __restrict__ A, const float* __restrict__ W,
                           const float* __restrict__ bias, float* __restrict__ out)
{
    int idx = blockIdx.x * blockDim.x + threadIdx.x;
    if (idx >= 2560) return;
    int n = idx / 10, j = idx - n * 10;
    const float* a = A + n * 1024;
    const float* w = W + j * 1024;
    float s = bias[j];
    for (int k = 0; k < 1024; k += 4)
        s += a[k] * w[k] + a[k + 1] * w[k + 1] + a[k + 2] * w[k + 2] + a[k + 3] * w[k + 3];
    out[idx] = s;
}

// ================= launch ======================================================
extern "C" void kernel_launch(void* const* d_in, const int* in_sizes, int n_in,
                              void* d_out, int out_size)
{
    (void)in_sizes; (void)n_in; (void)out_size;
    const float* x = (const float*)d_in[0];
    const float* a[6]  = {(const float*)d_in[1],  (const float*)d_in[4],  (const float*)d_in[7],
                          (const float*)d_in[10], (const float*)d_in[13], (const float*)d_in[16]};
    const float* bt[6] = {(const float*)d_in[2],  (const float*)d_in[5],  (const float*)d_in[8],
                          (const float*)d_in[11], (const float*)d_in[14], (const float*)d_in[17]};
    const float* cb[6] = {(const float*)d_in[3],  (const float*)d_in[6],  (const float*)d_in[9],
                          (const float*)d_in[12], (const float*)d_in[15], (const float*)d_in[18]};
    const float* gamma = (const float*)d_in[19];
    const float* beta  = (const float*)d_in[20];
    const float* fc1w  = (const float*)d_in[21];
    const float* fc1b  = (const float*)d_in[22];
    const float* fc2w  = (const float*)d_in[23];
    const float* fc2b  = (const float*)d_in[24];
    const float* noise = (const float*)d_in[25];

    __half *w2q, *w3q, *w4q, *w5q, *w6q, *p1, *p2, *p3, *p4, *p5;
    cudaGetSymbolAddress((void**)&w2q, g_w2q);
    cudaGetSymbolAddress((void**)&w3q, g_w3q);
    cudaGetSymbolAddress((void**)&w4q, g_w4q);
    cudaGetSymbolAddress((void**)&w5q, g_w5q);
    cudaGetSymbolAddress((void**)&w6q, g_w6q);
    cudaGetSymbolAddress((void**)&p1, g_p1);
    cudaGetSymbolAddress((void**)&p2, g_p2);
    cudaGetSymbolAddress((void**)&p3, g_p3);
    cudaGetSymbolAddress((void**)&p4, g_p4);
    cudaGetSymbolAddress((void**)&p5, g_p5);

    float *z6, *zbn, *fc1o, *scale, *shift;
    cudaGetSymbolAddress((void**)&z6,  g_z6);
    cudaGetSymbolAddress((void**)&zbn, g_zbn);
    cudaGetSymbolAddress((void**)&fc1o, g_fc1o);
    cudaGetSymbolAddress((void**)&scale, g_bnscale);
    cudaGetSymbolAddress((void**)&shift, g_bnshift);

    constexpr int SMEM_MMA = 2 * (3 * 128 + 2 * 128) * 72 * 2;   // 184320 B
    auto k2 = conv_mma<128, 128, 32, 32, 2, false>;
    auto k3 = conv_mma<128, 256, 16, 16, 1, false>;
    auto k4 = conv_mma<256, 256, 16, 16, 2, false>;
    auto k5 = conv_mma<256, 512, 8,  8,  1, false>;
    auto k6 = conv_mma<512, 512, 8,  8,  2, true>;
    cudaFuncSetAttribute(k2, cudaFuncAttributeMaxDynamicSharedMemorySize, SMEM_MMA);
    cudaFuncSetAttribute(k3, cudaFuncAttributeMaxDynamicSharedMemorySize, SMEM_MMA);
    cudaFuncSetAttribute(k4, cudaFuncAttributeMaxDynamicSharedMemorySize, SMEM_MMA);
    cudaFuncSetAttribute(k5, cudaFuncAttributeMaxDynamicSharedMemorySize, SMEM_MMA);
    cudaFuncSetAttribute(k6, cudaFuncAttributeMaxDynamicSharedMemorySize, SMEM_MMA);

    // 0: weight prep
    prepw<<<(4574592 + 255) / 256, 256>>>(a[0], bt[0], a[1], bt[1], a[2], bt[2],
                                          a[3], bt[3], a[4], bt[4], a[5], bt[5]);
    // 1: L1 SIMT -> planes p1
    conv1<<<dim3(16, 4, 128), 128>>>(x, cb[0], p1);
    // 2: L2 128->128, 32->16, s2: 65536 px -> 512 tiles, COUT=128 -> 1 co-block
    k2<<<dim3(512, 1), 512, SMEM_MMA>>>(w2q, p1, cb[1], p2, nullptr, nullptr);
    // 3: L3 128->256, 16x16: 512 tiles x 2 co-blocks
    k3<<<dim3(512, 2), 512, SMEM_MMA>>>(w3q, p2, cb[2], p3, nullptr, nullptr);
    // 4: L4 256->256, 16->8, s2: 128 tiles x 2 co-blocks
    k4<<<dim3(128, 2), 512, SMEM_MMA>>>(w4q, p3, cb[3], p4, nullptr, nullptr);
    // 5: L5 256->512, 8x8: 128 tiles x 4 co-blocks  <- ncu -s 5 target
    k5<<<dim3(128, 4), 512, SMEM_MMA>>>(w5q, p4, cb[4], p5, nullptr, nullptr);
    // 6: L6 512->512, 8->4, s2, sampled: 32 tiles x 4 co-blocks
    k6<<<dim3(32, 4), 512, SMEM_MMA>>>(w6q, p5, cb[5], nullptr, z6, noise);

    bn_stats<<<512, 256>>>(z6, gamma, beta, scale, shift);
    bn_norm<<<(2097152 + 255) / 256, 256>>>(z6, scale, shift, zbn);
    fc1_kernel<<<dim3(16, 4), 256>>>(zbn, fc1w, fc1b, fc1o);
    fc2_kernel<<<(2560 + 127) / 128, 128>>>(fc1o, fc2w, fc2b, (float*)d_out);
}

// round 15
// speedup vs baseline: 1.5146x; 1.1690x over previous
#include <cuda_runtime.h>
#include <cuda_fp16.h>
#include <math.h>
#include <stdint.h>

#define EPS 1e-5f

// ================= device scratch (no runtime allocation allowed) ==============
__device__ float g_wm1[3456], g_wv1[3456];

// weight variants, K-major [2][COUT*9*CIN] fp16 : 0=wm(rn) 1=wv
__device__ __half g_w2q[294912];
__device__ __half g_w3q[589824];
__device__ __half g_w4q[1179648];
__device__ __half g_w5q[2359296];
__device__ __half g_w6q[4718592];

// activation NHWC fp16 planes: [2][N*H*W*C] : 0=x(rn) 1=s=x^2
__device__ __half g_p1[67108864];   // 2*(256,32,32,128)
__device__ __half g_p2[16777216];   // 2*(256,16,16,128)
__device__ __half g_p3[33554432];   // 2*(256,16,16,256)
__device__ __half g_p4[8388608];    // 2*(256,8,8,256)
__device__ __half g_p5[16777216];   // 2*(256,8,8,512)

__device__ float g_z6[2097152];   // [256,512,4,4] fp32 NCHW
__device__ float g_zbn[2097152];
__device__ float g_fc1o[262144];
__device__ float g_bnscale[512], g_bnshift[512];

// ================= packed f32x2 helpers (SIMT L1) ==============================
__device__ __forceinline__ unsigned long long bcast2(float x) {
    unsigned long long r; unsigned u = __float_as_uint(x);
    asm("mov.b64 %0, {%1, %1};" : "=l"(r) : "r"(u));
    return r;
}
__device__ __forceinline__ unsigned long long mul2(unsigned long long a, unsigned long long b) {
    unsigned long long d;
    asm("mul.rn.f32x2 %0, %1, %2;" : "=l"(d) : "l"(a), "l"(b));
    return d;
}
__device__ __forceinline__ void fma2(unsigned long long& d, unsigned long long a, unsigned long long b) {
    asm("fma.rn.f32x2 %0, %1, %2, %0;" : "+l"(d) : "l"(a), "l"(b));
}
__device__ __forceinline__ void unpack2(unsigned long long v, float& lo, float& hi) {
    unsigned ulo, uhi;
    asm("mov.b64 {%0, %1}, %2;" : "=r"(ulo), "=r"(uhi) : "l"(v));
    lo = __uint_as_float(ulo); hi = __uint_as_float(uhi);
}

// fp16 pair pack: low half = first element
__device__ __forceinline__ uint32_t pkh2(float a, float b) {
    uint32_t lo = (uint32_t)__half_as_ushort(__float2half_rn(a));
    uint32_t hi = (uint32_t)__half_as_ushort(__float2half_rn(b));
    return lo | (hi << 16);
}

// mma.sync m16n8k16 fp16 -> f32
#define MMA16816(C, A, B) asm volatile( \
    "mma.sync.aligned.m16n8k16.row.col.f32.f16.f16.f32 " \
    "{%0,%1,%2,%3},{%4,%5,%6,%7},{%8,%9},{%0,%1,%2,%3};" \
    : "+f"((C)[0]), "+f"((C)[1]), "+f"((C)[2]), "+f"((C)[3]) \
    : "r"((A)[0]), "r"((A)[1]), "r"((A)[2]), "r"((A)[3]), \
      "r"((B)[0]), "r"((B)[1]))

#define LDMX4(R, ADDR) asm volatile( \
    "ldmatrix.sync.aligned.m8n8.x4.shared.b16 {%0,%1,%2,%3}, [%4];" \
    : "=r"((R)[0]), "=r"((R)[1]), "=r"((R)[2]), "=r"((R)[3]) : "r"(ADDR))

// 16B async copy, global -> shared, L1-bypass; sz=0 zero-fills
__device__ __forceinline__ void cpa16(uint32_t dst, const void* src, int sz) {
    asm volatile("cp.async.cg.shared.global [%0], [%1], 16, %2;"
                 :: "r"(dst), "l"(src), "r"(sz));
}
__device__ __forceinline__ void cpa_commit() {
    asm volatile("cp.async.commit_group;" ::: "memory");
}
__device__ __forceinline__ void cpa_wait0() {
    asm volatile("cp.async.wait_group 0;" ::: "memory");
}

// ================= weight preprocessing (one launch) ===========================
__global__ void prepw(const float* __restrict__ a1, const float* __restrict__ b1,
                      const float* __restrict__ a2, const float* __restrict__ b2,
                      const float* __restrict__ a3, const float* __restrict__ b3,
                      const float* __restrict__ a4, const float* __restrict__ b4,
                      const float* __restrict__ a5, const float* __restrict__ b5,
                      const float* __restrict__ a6, const float* __restrict__ b6)
{
    int i = blockIdx.x * blockDim.x + threadIdx.x;
    if (i >= 4574592) return;

    const float *A, *Bp; int j, cin; __half* WQ; int wplane; bool l1 = false;
    if (i < 150912) {
        if (i < 3456) { A = a1; Bp = b1; j = i; l1 = true; cin = 3; WQ = nullptr; wplane = 0; }
        else          { A = a2; Bp = b2; j = i - 3456;   cin = 128; WQ = g_w2q; wplane = 147456; }
    } else if (i < 1035648) {
        if (i < 445824) { A = a3; Bp = b3; j = i - 150912; cin = 128; WQ = g_w3q; wplane = 294912; }
        else            { A = a4; Bp = b4; j = i - 445824; cin = 256; WQ = g_w4q; wplane = 589824; }
    } else {
        if (i < 2215296) { A = a5; Bp = b5; j = i - 1035648; cin = 256; WQ = g_w5q; wplane = 1179648; }
        else             { A = a6; Bp = b6; j = i - 2215296; cin = 512; WQ = g_w6q; wplane = 2359296; }
    }
    float p0 = 1.f / (1.f + expf(-A[j]));
    float sb = 1.f / (1.f + expf(-Bp[j]));
    float p1 = (1.f - p0) * sb;
    float m  = 2.f * p1 + p0 - 1.f;
    float v  = (1.f - p0) - m * m;
    if (l1) { g_wm1[j] = m; g_wv1[j] = v; return; }
    int k9 = cin * 9;
    int co  = j / k9;
    int r   = j - co * k9;
    int ci  = r / 9;
    int tap = r - ci * 9;
    int o   = co * k9 + tap * cin + ci;
    WQ[o]          = __float2half_rn(m);
    WQ[wplane + o] = __float2half_rn(v);
}

// ================= L1 conv (SIMT, CIN=3) -> NHWC fp16 planes ===================
__global__ void __launch_bounds__(128)
conv1(const float* __restrict__ in, const float* __restrict__ bias,
      __half* __restrict__ pout)
{
    constexpr int CIN = 3, HIN = 32, WIN = 32, CK = 3;
    constexpr int TCO = 32, IPH = 10, IPW = 12;
    constexpr int XS_N = 2 * CK * IPH * IPW;
    constexpr int WS_N = CK * 9 * TCO;
    constexpr int NXV = 10, NF4 = 3, CP = 2, PX_T = 8;
    constexpr int OPLANE = 256 * 32 * 32 * 128;

    __shared__ __align__(16) float xs[XS_N];
    __shared__ __align__(16) float wsm[WS_N];
    __shared__ __align__(16) float wsv[WS_N];

    const int tid = threadIdx.x;
    const int tileX = blockIdx.x % 4, tileY = blockIdx.x / 4;
    const int coBase = blockIdx.y * TCO;
    const int nBase  = blockIdx.z * 2;
    const int oy0 = tileY * 8, ox0 = tileX * 8;

    const int co0 = (tid % 8) * 4;
    const int pg  = tid / 8;
    const int img = pg / 8;
    const int py  = pg % 8;

    unsigned long long aM[CP][PX_T], aV[CP][PX_T];
    #pragma unroll
    for (int p = 0; p < CP; p++)
        #pragma unroll
        for (int i = 0; i < PX_T; i++) { aM[p][i] = 0ull; aV[p][i] = 0ull; }

    for (int idx = tid; idx < XS_N; idx += 128) {
        int im = idx / (CK * IPH * IPW);
        int r  = idx - im * (CK * IPH * IPW);
        int ck = r / (IPH * IPW);
        int r2 = r - ck * (IPH * IPW);
        int iy = r2 / IPW;
        int ix = r2 - iy * IPW;
        int gy = oy0 - 1 + iy, gx = ox0 - 1 + ix;
        float v = 0.f;
        if (gy >= 0 && gy < HIN && gx >= 0 && gx < WIN)
            v = in[(((nBase + im) * CIN + ck) * HIN + gy) * WIN + gx];
        xs[idx] = v;
    }
    for (int idx = tid; idx < WS_N; idx += 128) {
        int ck  = idx / (9 * TCO);
        int rm  = idx - ck * (9 * TCO);
        int tap = rm / TCO;
        int co  = rm - tap * TCO;
        int g = ((coBase + co) * CIN + ck) * 9 + tap;
        wsm[idx] = g_wm1[g];
        wsv[idx] = g_wv1[g];
    }
    __syncthreads();

    #pragma unroll 1
    for (int ck = 0; ck < CK; ck++) {
        #pragma unroll
        for (int ky = 0; ky < 3; ky++) {
            const float* xrow = &xs[((img * CK + ck) * IPH + (py + ky)) * IPW];
            float4 f4[NF4];
            #pragma unroll
            for (int j = 0; j < NF4; j++)
                f4[j] = reinterpret_cast<const float4*>(xrow)[j];
            const float* xv = reinterpret_cast<const float*>(f4);
            unsigned long long xp[NXV], xxp[NXV];
            #pragma unroll
            for (int j = 0; j < NXV; j++) {
                xp[j]  = bcast2(xv[j]);
                xxp[j] = mul2(xp[j], xp[j]);
            }
            #pragma unroll
            for (int kx = 0; kx < 3; kx++) {
                const int tap = ky * 3 + kx;
                ulonglong2 m2 = *reinterpret_cast<const ulonglong2*>(&wsm[(ck * 9 + tap) * TCO + co0]);
                ulonglong2 v2 = *reinterpret_cast<const ulonglong2*>(&wsv[(ck * 9 + tap) * TCO + co0]);
                #pragma unroll
                for (int i = 0; i < PX_T; i++) {
                    fma2(aM[0][i], m2.x, xp[kx + i]);
                    fma2(aM[1][i], m2.y, xp[kx + i]);
                    fma2(aV[0][i], v2.x, xxp[kx + i]);
                    fma2(aV[1][i], v2.y, xxp[kx + i]);
                }
            }
        }
    }

    const int n = nBase + img;
    const int oy = oy0 + py;
    #pragma unroll
    for (int p = 0; p < CP; p++) {
        const int cA = coBase + co0 + 2 * p;
        const float bA = bias[cA], bB = bias[cA + 1];
        #pragma unroll
        for (int i = 0; i < PX_T; i++) {
            float mA, mB, vA, vB;
            unpack2(aM[p][i], mA, mB);
            unpack2(aV[p][i], vA, vB);
            mA += bA; mB += bB;
            float hA = erff(mA * rsqrtf(2.f * (vA + EPS)));
            float hB = erff(mB * rsqrtf(2.f * (vB + EPS)));
            int oi = ((n * 32 + oy) * 32 + (ox0 + i)) * 128 + cA;
            *(uint32_t*)&pout[oi]          = pkh2(hA, hB);
            *(uint32_t*)&pout[OPLANE + oi] = pkh2(hA * hA, hB * hB);
        }
    }
}

// ================= mma.sync conv layers 2-6 (v7: 2-product scheme) =============
// Block: 128px x 128co, 16 warps (512 thr), warp = 32px x 32co (mt=2, nt=4).
// m = x_rn * wm ; v = s * wv    (2 MMAs per microtile)
// Double-buffered cp.async; next-stage issue overlapped after ks0.
template<int CIN, int COUT, int HIN, int WIN, int S, bool LAST>
__global__ void __launch_bounds__(512, 1)
conv_mma(const __half* __restrict__ wq,    // [2][COUT*9CIN] : wm, wv
         const __half* __restrict__ pin,   // [2 planes][256*HIN*WIN*CIN]
         const float* __restrict__ bias,
         __half* __restrict__ pout,        // planes (if !LAST)
         float* __restrict__ zout,         // NCHW fp32 (if LAST)
         const float* __restrict__ noise)
{
    constexpr int HO = HIN / S, WO = WIN / S;
    constexpr int PIX = HO * WO;
    constexpr int CG = CIN / 64;
    constexpr int NS = 9 * CG;
    constexpr int K9 = 9 * CIN;
    constexpr int WPLANE = COUT * K9;
    constexpr int IPLANE = 256 * HIN * WIN * CIN;
    constexpr int OPLANE = 256 * HO * WO * COUT;
    constexpr int AST = 72;                  // padded row stride (144 B)
    constexpr int APL = 128 * AST;           // A plane: 128 pixel rows
    constexpr int BPL = 128 * AST;           // B plane: 128 cout rows
    constexpr uint32_t BUF = (uint32_t)(2 * APL + 2 * BPL) * 2;  // 73728 B / stage

    extern __shared__ __align__(16) __half sm[];

    const int tid = threadIdx.x;
    const int wid = tid >> 5, lid = tid & 31;
    const int g = lid >> 2, t = lid & 3;
    const int wpx = wid >> 2, wco = wid & 3;     // 4 px-quarters x 4 co-quarters
    const int pixBase = blockIdx.x * 128;
    const int coBase  = blockIdx.y * 128;

    const uint32_t smb = (uint32_t)__cvta_generic_to_shared(sm);
    const int arow = (lid & 7) + ((lid >> 3) & 1) * 8;
    const int achk = ((lid >> 4) & 1) * 8;
    const int brow = (lid & 7) + ((lid >> 4) & 1) * 8;
    const int bchk = ((lid >> 3) & 1) * 8;
    const uint32_t aAddr0 = smb + (uint32_t)(((wpx * 32 + arow) * AST + achk) * 2);
    const uint32_t bAddr0 = smb + (uint32_t)(2 * APL * 2) +
                            (uint32_t)(((wco * 32 + brow) * AST + bchk) * 2);

    // staging: 2 A planes x 128 rows + 2 B variants x 128 rows = 512 row jobs
    auto stage = [&](int s, uint32_t bofs) {
        const int tap = s / CG, cg = s - tap * CG;
        const int ky = tap / 3, kx = tap - ky * 3;
        const int c0 = cg * 64;
        const int j = tid;   // exactly one job per thread (512 jobs / 512 thr)
        if (j < 256) {
            const int pl = j >> 7, row = j & 127;
            const int gp = pixBase + row;
            const int n  = gp / PIX;
            const int r  = gp - n * PIX;
            const int oy = r / WO, ox = r - (r / WO) * WO;
            const int iy = oy * S - 1 + ky, ix = ox * S - 1 + kx;
            uint32_t dst = smb + bofs + (uint32_t)((pl * APL + row * AST) * 2);
            const bool ok = (iy >= 0 && iy < HIN && ix >= 0 && ix < WIN);
            const __half* src = ok
                ? pin + (size_t)pl * IPLANE + ((size_t)(n * HIN + iy) * WIN + ix) * CIN + c0
                : pin;
            const int sz = ok ? 16 : 0;
            #pragma unroll
            for (int q = 0; q < 8; q++)
                cpa16(dst + q * 16, src + q * 8, sz);
        } else {
            const int jj = j - 256;
            const int var = jj >> 7, row = jj & 127;
            const __half* src = wq + (size_t)var * WPLANE +
                                (size_t)(coBase + row) * K9 + tap * CIN + c0;
            uint32_t dst = smb + bofs + (uint32_t)((2 * APL + var * BPL + row * AST) * 2);
            #pragma unroll
            for (int q = 0; q < 8; q++)
                cpa16(dst + q * 16, src + q * 8, 16);
        }
    };

    float accM[2][4][4], accV[2][4][4];
    #pragma unroll
    for (int mt = 0; mt < 2; mt++)
        #pragma unroll
        for (int nt = 0; nt < 4; nt++)
            #pragma unroll
            for (int e = 0; e < 4; e++) { accM[mt][nt][e] = 0.f; accV[mt][nt][e] = 0.f; }

    // one k-step of compute on buffer bofs
    auto compute_ks = [&](int ks, uint32_t bofs) {
        const uint32_t ksb = (uint32_t)(ks * 32) + bofs;
        uint32_t bm[2][4], bv[2][4];
        #pragma unroll
        for (int ntp = 0; ntp < 2; ntp++) {
            const uint32_t b0 = bAddr0 + (uint32_t)(ntp * 16 * AST * 2) + ksb;
            LDMX4(bm[ntp], b0);
            LDMX4(bv[ntp], b0 + (uint32_t)(BPL * 2));
        }
        uint32_t ax[2][4], as_[2][4];
        #pragma unroll
        for (int mt = 0; mt < 2; mt++) {
            const uint32_t a0 = aAddr0 + (uint32_t)(mt * 16 * AST * 2) + ksb;
            LDMX4(ax[mt], a0);
            LDMX4(as_[mt], a0 + (uint32_t)(APL * 2));
        }
        #pragma unroll
        for (int mt = 0; mt < 2; mt++)
            #pragma unroll
            for (int nt = 0; nt < 4; nt++) {
                const int ntp = nt >> 1, o = (nt & 1) * 2;
                MMA16816(accM[mt][nt], ax[mt],  &bm[ntp][o]);
                MMA16816(accV[mt][nt], as_[mt], &bv[ntp][o]);
            }
    };

    stage(0, 0);
    cpa_commit();

    #pragma unroll 1
    for (int s = 0; s < NS; s++) {
        cpa_wait0();          // buffer s ready (only group s pending)
        __syncthreads();
        const uint32_t bofs = (uint32_t)(s & 1) * BUF;

        compute_ks(0, bofs);
        if (s + 1 < NS) {     // overlap next-stage issue with remaining compute
            stage(s + 1, (uint32_t)((s + 1) & 1) * BUF);
            cpa_commit();
        }
        compute_ks(1, bofs);
        compute_ks(2, bofs);
        compute_ks(3, bofs);
        __syncthreads();      // all warps done with buffer s before it is restaged
    }

    // ---- epilogue ----
    #pragma unroll
    for (int mt = 0; mt < 2; mt++)
        #pragma unroll
        for (int nt = 0; nt < 4; nt++) {
            const int co0 = coBase + wco * 32 + nt * 8 + 2 * t;
            const float b0 = bias[co0], b1 = bias[co0 + 1];
            #pragma unroll
            for (int h2 = 0; h2 < 2; h2++) {
                const int gp = pixBase + wpx * 32 + mt * 16 + g + h2 * 8;
                float m0 = accM[mt][nt][2 * h2]     + b0;
                float m1 = accM[mt][nt][2 * h2 + 1] + b1;
                float v0 = accV[mt][nt][2 * h2];
                float v1 = accV[mt][nt][2 * h2 + 1];
                const int n = gp / PIX;
                const int r = gp - n * PIX;
                const int oy = r / WO, ox = r - (r / WO) * WO;
                if (LAST) {
                    int o0 = ((n * COUT + co0) * HO + oy) * WO + ox;
                    int o1 = o0 + HO * WO;
                    zout[o0] = m0 + sqrtf(v0 + EPS) * noise[o0];
                    zout[o1] = m1 + sqrtf(v1 + EPS) * noise[o1];
                } else {
                    float h0 = erff(m0 * rsqrtf(2.f * (v0 + EPS)));
                    float h1 = erff(m1 * rsqrtf(2.f * (v1 + EPS)));
                    int oi = ((n * HO + oy) * WO + ox) * COUT + co0;
                    *(uint32_t*)&pout[oi]          = pkh2(h0, h1);
                    *(uint32_t*)&pout[OPLANE + oi] = pkh2(h0 * h0, h1 * h1);
                }
            }
        }
}

// ================= batchnorm / FC ==============================================
__global__ void bn_stats(const float* __restrict__ z, const float* __restrict__ gamma,
                         const float* __restrict__ beta, float* __restrict__ scale,
                         float* __restrict__ shift)
{
    __shared__ double ssum[256], ssq[256];
    int c = blockIdx.x, t = threadIdx.x;
    double s = 0.0, s2 = 0.0;
    for (int i = t; i < 4096; i += 256) {
        int n = i >> 4, qq = i & 15;
        float v = z[(n * 512 + c) * 16 + qq];
        s += v; s2 += (double)v * v;
    }
    ssum[t] = s; ssq[t] = s2;
    __syncthreads();
    for (int off = 128; off > 0; off >>= 1) {
        if (t < off) { ssum[t] += ssum[t + off]; ssq[t] += ssq[t + off]; }
        __syncthreads();
    }
    if (t == 0) {
        double mean = ssum[0] / 4096.0;
        double var  = ssq[0] / 4096.0 - mean * mean;
        float sc = gamma[c] * rsqrtf((float)var + EPS);
        scale[c] = sc;
        shift[c] = beta[c] - (float)mean * sc;
    }
}

__global__ void bn_norm(const float* __restrict__ z, const float* __restrict__ scale,
                        const float* __restrict__ shift, float* __restrict__ out)
{
    int idx = blockIdx.x * blockDim.x + threadIdx.x;
    if (idx < 256 * 8192) {
        int c = (idx >> 4) & 511;
        float v = z[idx] * scale[c] + shift[c];
        out[idx] = v > 0.f ? v : 0.f;
    }
}

__global__ void __launch_bounds__(256)
fc1_kernel(const float* __restrict__ A, const float* __restrict__ W,
           const float* __restrict__ bias, float* __restrict__ C)
{
    __shared__ float As[64][33];
    __shared__ float Ws[64][33];
    const int t = threadIdx.x;
    const int mBlk = blockIdx.y * 64, nBlk = blockIdx.x * 64;
    const int msub = (t % 16) * 4, nsub = (t / 16) * 4;
    float acc[4][4];
    #pragma unroll
    for (int i = 0; i < 4; i++)
        #pragma unroll
        for (int j = 0; j < 4; j++) acc[i][j] = 0.f;

    for (int k0 = 0; k0 < 8192; k0 += 32) {
        for (int i = t; i < 64 * 32; i += 256) {
            int r = i >> 5, kk = i & 31;
            As[r][kk] = A[(mBlk + r) * 8192 + k0 + kk];
            Ws[r][kk] = W[(nBlk + r) * 8192 + k0 + kk];
        }
        __syncthreads();
        #pragma unroll
        for (int kk = 0; kk < 32; kk++) {
            float a0 = As[msub][kk], a1 = As[msub + 1][kk], a2 = As[msub + 2][kk], a3 = As[msub + 3][kk];
            float w0 = Ws[nsub][kk], w1 = Ws[nsub + 1][kk], w2 = Ws[nsub + 2][kk], w3 = Ws[nsub + 3][kk];
            acc[0][0] += a0 * w0; acc[0][1] += a0 * w1; acc[0][2] += a0 * w2; acc[0][3] += a0 * w3;
            acc[1][0] += a1 * w0; acc[1][1] += a1 * w1; acc[1][2] += a1 * w2; acc[1][3] += a1 * w3;
            acc[2][0] += a2 * w0; acc[2][1] += a2 * w1; acc[2][2] += a2 * w2; acc[2][3] += a2 * w3;
            acc[3][0] += a3 * w0; acc[3][1] += a3 * w1; acc[3][2] += a3 * w2; acc[3][3] += a3 * w3;
        }
        __syncthreads();
    }
    #pragma unroll
    for (int i = 0; i < 4; i++)
        #pragma unroll
        for (int j = 0; j < 4; j++) {
            float v = acc[i][j] + bias[nBlk + nsub + j];
            C[(mBlk + msub + i) * 1024 + nBlk + nsub + j] = v > 0.f ? v : 0.f;
        }
}

__global__ void fc2_kernel(const float* __restrict__ A, const float* __restrict__ W,
                           const float* __restrict__ bias, float* __restrict__ out)
{
    int idx = blockIdx.x * blockDim.x + threadIdx.x;
    if (idx >= 2560) return;
    int n = idx / 10, j = idx - n * 10;
    const float* a = A + n * 1024;
    const float* w = W + j * 1024;
    float s = bias[j];
    for (int k = 0; k < 1024; k += 4)
        s += a[k] * w[k] + a[k + 1] * w[k + 1] + a[k + 2] * w[k + 2] + a[k + 3] * w[k + 3];
    out[idx] = s;
}

// ================= launch ======================================================
extern "C" void kernel_launch(void* const* d_in, const int* in_sizes, int n_in,
                              void* d_out, int out_size)
{
    (void)in_sizes; (void)n_in; (void)out_size;
    const float* x = (const float*)d_in[0];
    const float* a[6]  = {(const float*)d_in[1],  (const float*)d_in[4],  (const float*)d_in[7],
                          (const float*)d_in[10], (const float*)d_in[13], (const float*)d_in[16]};
    const float* bt[6] = {(const float*)d_in[2],  (const float*)d_in[5],  (const float*)d_in[8],
                          (const float*)d_in[11], (const float*)d_in[14], (const float*)d_in[17]};
    const float* cb[6] = {(const float*)d_in[3],  (const float*)d_in[6],  (const float*)d_in[9],
                          (const float*)d_in[12], (const float*)d_in[15], (const float*)d_in[18]};
    const float* gamma = (const float*)d_in[19];
    const float* beta  = (const float*)d_in[20];
    const float* fc1w  = (const float*)d_in[21];
    const float* fc1b  = (const float*)d_in[22];
    const float* fc2w  = (const float*)d_in[23];
    const float* fc2b  = (const float*)d_in[24];
    const float* noise = (const float*)d_in[25];

    __half *w2q, *w3q, *w4q, *w5q, *w6q, *p1, *p2, *p3, *p4, *p5;
    cudaGetSymbolAddress((void**)&w2q, g_w2q);
    cudaGetSymbolAddress((void**)&w3q, g_w3q);
    cudaGetSymbolAddress((void**)&w4q, g_w4q);
    cudaGetSymbolAddress((void**)&w5q, g_w5q);
    cudaGetSymbolAddress((void**)&w6q, g_w6q);
    cudaGetSymbolAddress((void**)&p1, g_p1);
    cudaGetSymbolAddress((void**)&p2, g_p2);
    cudaGetSymbolAddress((void**)&p3, g_p3);
    cudaGetSymbolAddress((void**)&p4, g_p4);
    cudaGetSymbolAddress((void**)&p5, g_p5);

    float *z6, *zbn, *fc1o, *scale, *shift;
    cudaGetSymbolAddress((void**)&z6,  g_z6);
    cudaGetSymbolAddress((void**)&zbn, g_zbn);
    cudaGetSymbolAddress((void**)&fc1o, g_fc1o);
    cudaGetSymbolAddress((void**)&scale, g_bnscale);
    cudaGetSymbolAddress((void**)&shift, g_bnshift);

    constexpr int SMEM_MMA = 2 * (2 * 128 + 2 * 128) * 72 * 2;   // 147456 B
    auto k2 = conv_mma<128, 128, 32, 32, 2, false>;
    auto k3 = conv_mma<128, 256, 16, 16, 1, false>;
    auto k4 = conv_mma<256, 256, 16, 16, 2, false>;
    auto k5 = conv_mma<256, 512, 8,  8,  1, false>;
    auto k6 = conv_mma<512, 512, 8,  8,  2, true>;
    cudaFuncSetAttribute(k2, cudaFuncAttributeMaxDynamicSharedMemorySize, SMEM_MMA);
    cudaFuncSetAttribute(k3, cudaFuncAttributeMaxDynamicSharedMemorySize, SMEM_MMA);
    cudaFuncSetAttribute(k4, cudaFuncAttributeMaxDynamicSharedMemorySize, SMEM_MMA);
    cudaFuncSetAttribute(k5, cudaFuncAttributeMaxDynamicSharedMemorySize, SMEM_MMA);
    cudaFuncSetAttribute(k6, cudaFuncAttributeMaxDynamicSharedMemorySize, SMEM_MMA);

    // 0: weight prep
    prepw<<<(4574592 + 255) / 256, 256>>>(a[0], bt[0], a[1], bt[1], a[2], bt[2],
                                          a[3], bt[3], a[4], bt[4], a[5], bt[5]);
    // 1: L1 SIMT -> planes p1
    conv1<<<dim3(16, 4, 128), 128>>>(x, cb[0], p1);
    // 2: L2 128->128, 32->16, s2: 65536 px -> 512 tiles, COUT=128 -> 1 co-block
    k2<<<dim3(512, 1), 512, SMEM_MMA>>>(w2q, p1, cb[1], p2, nullptr, nullptr);
    // 3: L3 128->256, 16x16: 512 tiles x 2 co-blocks
    k3<<<dim3(512, 2), 512, SMEM_MMA>>>(w3q, p2, cb[2], p3, nullptr, nullptr);
    // 4: L4 256->256, 16->8, s2: 128 tiles x 2 co-blocks
    k4<<<dim3(128, 2), 512, SMEM_MMA>>>(w4q, p3, cb[3], p4, nullptr, nullptr);
    // 5: L5 256->512, 8x8: 128 tiles x 4 co-blocks  <- ncu -s 5 target
    k5<<<dim3(128, 4), 512, SMEM_MMA>>>(w5q, p4, cb[4], p5, nullptr, nullptr);
    // 6: L6 512->512, 8->4, s2, sampled: 32 tiles x 4 co-blocks
    k6<<<dim3(32, 4), 512, SMEM_MMA>>>(w6q, p5, cb[5], nullptr, z6, noise);

    bn_stats<<<512, 256>>>(z6, gamma, beta, scale, shift);
    bn_norm<<<(2097152 + 255) / 256, 256>>>(z6, scale, shift, zbn);
    fc1_kernel<<<dim3(16, 4), 256>>>(zbn, fc1w, fc1b, fc1o);
    fc2_kernel<<<(2560 + 127) / 128, 128>>>(fc1o, fc2w, fc2b, (float*)d_out);
}

// round 16
// speedup vs baseline: 1.7135x; 1.1313x over previous
#include <cuda_runtime.h>
#include <cuda_fp16.h>
#include <math.h>
#include <stdint.h>

#define EPS 1e-5f

// ================= device scratch (no runtime allocation allowed) ==============
__device__ float g_wm1[3456], g_wv1[3456];

// weight variants, K-major [2][COUT*9*CIN] fp16 : 0=wm(rn) 1=wv
__device__ __half g_w2q[294912];
__device__ __half g_w3q[589824];
__device__ __half g_w4q[1179648];
__device__ __half g_w5q[2359296];
__device__ __half g_w6q[4718592];

// activation NHWC fp16 planes: [2][N*H*W*C] : 0=x(rn) 1=s=x^2
__device__ __half g_p1[67108864];   // 2*(256,32,32,128)
__device__ __half g_p2[16777216];   // 2*(256,16,16,128)
__device__ __half g_p3[33554432];   // 2*(256,16,16,256)
__device__ __half g_p4[8388608];    // 2*(256,8,8,256)
__device__ __half g_p5[16777216];   // 2*(256,8,8,512)

__device__ float g_z6[2097152];   // [256,512,4,4] fp32 NCHW
__device__ float g_zbn[2097152];
__device__ float g_fc1p[524288];  // [2 k-splits][256*1024] fc1 partials
__device__ float g_fc1o[262144];
__device__ float g_bnscale[512], g_bnshift[512];

// ================= packed f32x2 helpers ========================================
__device__ __forceinline__ unsigned long long bcast2(float x) {
    unsigned long long r; unsigned u = __float_as_uint(x);
    asm("mov.b64 %0, {%1, %1};" : "=l"(r) : "r"(u));
    return r;
}
__device__ __forceinline__ unsigned long long pkf2(float a, float b) {
    unsigned long long r;
    asm("mov.b64 %0, {%1, %2};" : "=l"(r) : "f"(a), "f"(b));
    return r;
}
__device__ __forceinline__ unsigned long long mul2(unsigned long long a, unsigned long long b) {
    unsigned long long d;
    asm("mul.rn.f32x2 %0, %1, %2;" : "=l"(d) : "l"(a), "l"(b));
    return d;
}
__device__ __forceinline__ void fma2(unsigned long long& d, unsigned long long a, unsigned long long b) {
    asm("fma.rn.f32x2 %0, %1, %2, %0;" : "+l"(d) : "l"(a), "l"(b));
}
__device__ __forceinline__ void unpack2(unsigned long long v, float& lo, float& hi) {
    unsigned ulo, uhi;
    asm("mov.b64 {%0, %1}, %2;" : "=r"(ulo), "=r"(uhi) : "l"(v));
    lo = __uint_as_float(ulo); hi = __uint_as_float(uhi);
}

// fp16 pair pack: low half = first element
__device__ __forceinline__ uint32_t pkh2(float a, float b) {
    uint32_t lo = (uint32_t)__half_as_ushort(__float2half_rn(a));
    uint32_t hi = (uint32_t)__half_as_ushort(__float2half_rn(b));
    return lo | (hi << 16);
}

// mma.sync m16n8k16 fp16 -> f32
#define MMA16816(C, A, B) asm volatile( \
    "mma.sync.aligned.m16n8k16.row.col.f32.f16.f16.f32 " \
    "{%0,%1,%2,%3},{%4,%5,%6,%7},{%8,%9},{%0,%1,%2,%3};" \
    : "+f"((C)[0]), "+f"((C)[1]), "+f"((C)[2]), "+f"((C)[3]) \
    : "r"((A)[0]), "r"((A)[1]), "r"((A)[2]), "r"((A)[3]), \
      "r"((B)[0]), "r"((B)[1]))

#define LDMX4(R, ADDR) asm volatile( \
    "ldmatrix.sync.aligned.m8n8.x4.shared.b16 {%0,%1,%2,%3}, [%4];" \
    : "=r"((R)[0]), "=r"((R)[1]), "=r"((R)[2]), "=r"((R)[3]) : "r"(ADDR))

// 16B async copy, global -> shared, L1-bypass; sz=0 zero-fills
__device__ __forceinline__ void cpa16(uint32_t dst, const void* src, int sz) {
    asm volatile("cp.async.cg.shared.global [%0], [%1], 16, %2;"
                 :: "r"(dst), "l"(src), "r"(sz));
}
__device__ __forceinline__ void cpa_commit() {
    asm volatile("cp.async.commit_group;" ::: "memory");
}
__device__ __forceinline__ void cpa_wait0() {
    asm volatile("cp.async.wait_group 0;" ::: "memory");
}

// ================= weight preprocessing (one launch) ===========================
__global__ void prepw(const float* __restrict__ a1, const float* __restrict__ b1,
                      const float* __restrict__ a2, const float* __restrict__ b2,
                      const float* __restrict__ a3, const float* __restrict__ b3,
                      const float* __restrict__ a4, const float* __restrict__ b4,
                      const float* __restrict__ a5, const float* __restrict__ b5,
                      const float* __restrict__ a6, const float* __restrict__ b6)
{
    int i = blockIdx.x * blockDim.x + threadIdx.x;
    if (i >= 4574592) return;

    const float *A, *Bp; int j, cin; __half* WQ; int wplane; bool l1 = false;
    if (i < 150912) {
        if (i < 3456) { A = a1; Bp = b1; j = i; l1 = true; cin = 3; WQ = nullptr; wplane = 0; }
        else          { A = a2; Bp = b2; j = i - 3456;   cin = 128; WQ = g_w2q; wplane = 147456; }
    } else if (i < 1035648) {
        if (i < 445824) { A = a3; Bp = b3; j = i - 150912; cin = 128; WQ = g_w3q; wplane = 294912; }
        else            { A = a4; Bp = b4; j = i - 445824; cin = 256; WQ = g_w4q; wplane = 589824; }
    } else {
        if (i < 2215296) { A = a5; Bp = b5; j = i - 1035648; cin = 256; WQ = g_w5q; wplane = 1179648; }
        else             { A = a6; Bp = b6; j = i - 2215296; cin = 512; WQ = g_w6q; wplane = 2359296; }
    }
    float p0 = 1.f / (1.f + expf(-A[j]));
    float sb = 1.f / (1.f + expf(-Bp[j]));
    float p1 = (1.f - p0) * sb;
    float m  = 2.f * p1 + p0 - 1.f;
    float v  = (1.f - p0) - m * m;
    if (l1) { g_wm1[j] = m; g_wv1[j] = v; return; }
    int k9 = cin * 9;
    int co  = j / k9;
    int r   = j - co * k9;
    int ci  = r / 9;
    int tap = r - ci * 9;
    int o   = co * k9 + tap * cin + ci;
    WQ[o]          = __float2half_rn(m);
    WQ[wplane + o] = __float2half_rn(v);
}

// ================= L1 conv (SIMT, CIN=3) -> NHWC fp16 planes ===================
__global__ void __launch_bounds__(128)
conv1(const float* __restrict__ in, const float* __restrict__ bias,
      __half* __restrict__ pout)
{
    constexpr int CIN = 3, HIN = 32, WIN = 32, CK = 3;
    constexpr int TCO = 32, IPH = 10, IPW = 12;
    constexpr int XS_N = 2 * CK * IPH * IPW;
    constexpr int WS_N = CK * 9 * TCO;
    constexpr int NXV = 10, NF4 = 3, CP = 2, PX_T = 8;
    constexpr int OPLANE = 256 * 32 * 32 * 128;

    __shared__ __align__(16) float xs[XS_N];
    __shared__ __align__(16) float wsm[WS_N];
    __shared__ __align__(16) float wsv[WS_N];

    const int tid = threadIdx.x;
    const int tileX = blockIdx.x % 4, tileY = blockIdx.x / 4;
    const int coBase = blockIdx.y * TCO;
    const int nBase  = blockIdx.z * 2;
    const int oy0 = tileY * 8, ox0 = tileX * 8;

    const int co0 = (tid % 8) * 4;
    const int pg  = tid / 8;
    const int img = pg / 8;
    const int py  = pg % 8;

    unsigned long long aM[CP][PX_T], aV[CP][PX_T];
    #pragma unroll
    for (int p = 0; p < CP; p++)
        #pragma unroll
        for (int i = 0; i < PX_T; i++) { aM[p][i] = 0ull; aV[p][i] = 0ull; }

    for (int idx = tid; idx < XS_N; idx += 128) {
        int im = idx / (CK * IPH * IPW);
        int r  = idx - im * (CK * IPH * IPW);
        int ck = r / (IPH * IPW);
        int r2 = r - ck * (IPH * IPW);
        int iy = r2 / IPW;
        int ix = r2 - iy * IPW;
        int gy = oy0 - 1 + iy, gx = ox0 - 1 + ix;
        float v = 0.f;
        if (gy >= 0 && gy < HIN && gx >= 0 && gx < WIN)
            v = in[(((nBase + im) * CIN + ck) * HIN + gy) * WIN + gx];
        xs[idx] = v;
    }
    for (int idx = tid; idx < WS_N; idx += 128) {
        int ck  = idx / (9 * TCO);
        int rm  = idx - ck * (9 * TCO);
        int tap = rm / TCO;
        int co  = rm - tap * TCO;
        int g = ((coBase + co) * CIN + ck) * 9 + tap;
        wsm[idx] = g_wm1[g];
        wsv[idx] = g_wv1[g];
    }
    __syncthreads();

    #pragma unroll 1
    for (int ck = 0; ck < CK; ck++) {
        #pragma unroll
        for (int ky = 0; ky < 3; ky++) {
            const float* xrow = &xs[((img * CK + ck) * IPH + (py + ky)) * IPW];
            float4 f4[NF4];
            #pragma unroll
            for (int j = 0; j < NF4; j++)
                f4[j] = reinterpret_cast<const float4*>(xrow)[j];
            const float* xv = reinterpret_cast<const float*>(f4);
            unsigned long long xp[NXV], xxp[NXV];
            #pragma unroll
            for (int j = 0; j < NXV; j++) {
                xp[j]  = bcast2(xv[j]);
                xxp[j] = mul2(xp[j], xp[j]);
            }
            #pragma unroll
            for (int kx = 0; kx < 3; kx++) {
                const int tap = ky * 3 + kx;
                ulonglong2 m2 = *reinterpret_cast<const ulonglong2*>(&wsm[(ck * 9 + tap) * TCO + co0]);
                ulonglong2 v2 = *reinterpret_cast<const ulonglong2*>(&wsv[(ck * 9 + tap) * TCO + co0]);
                #pragma unroll
                for (int i = 0; i < PX_T; i++) {
                    fma2(aM[0][i], m2.x, xp[kx + i]);
                    fma2(aM[1][i], m2.y, xp[kx + i]);
                    fma2(aV[0][i], v2.x, xxp[kx + i]);
                    fma2(aV[1][i], v2.y, xxp[kx + i]);
                }
            }
        }
    }

    const int n = nBase + img;
    const int oy = oy0 + py;
    #pragma unroll
    for (int p = 0; p < CP; p++) {
        const int cA = coBase + co0 + 2 * p;
        const float bA = bias[cA], bB = bias[cA + 1];
        #pragma unroll
        for (int i = 0; i < PX_T; i++) {
            float mA, mB, vA, vB;
            unpack2(aM[p][i], mA, mB);
            unpack2(aV[p][i], vA, vB);
            mA += bA; mB += bB;
            float hA = erff(mA * rsqrtf(2.f * (vA + EPS)));
            float hB = erff(mB * rsqrtf(2.f * (vB + EPS)));
            int oi = ((n * 32 + oy) * 32 + (ox0 + i)) * 128 + cA;
            *(uint32_t*)&pout[oi]          = pkh2(hA, hB);
            *(uint32_t*)&pout[OPLANE + oi] = pkh2(hA * hA, hB * hB);
        }
    }
}

// ================= mma.sync conv layers 2-6 (v7: 2-product scheme) =============
// Block: 128px x 128co, 16 warps (512 thr), warp = 32px x 32co (mt=2, nt=4).
// m = x_rn * wm ; v = s * wv    (2 MMAs per microtile)
// Double-buffered cp.async; next-stage issue overlapped after ks0.
template<int CIN, int COUT, int HIN, int WIN, int S, bool LAST>
__global__ void __launch_bounds__(512, 1)
conv_mma(const __half* __restrict__ wq,    // [2][COUT*9CIN] : wm, wv
         const __half* __restrict__ pin,   // [2 planes][256*HIN*WIN*CIN]
         const float* __restrict__ bias,
         __half* __restrict__ pout,        // planes (if !LAST)
         float* __restrict__ zout,         // NCHW fp32 (if LAST)
         const float* __restrict__ noise)
{
    constexpr int HO = HIN / S, WO = WIN / S;
    constexpr int PIX = HO * WO;
    constexpr int CG = CIN / 64;
    constexpr int NS = 9 * CG;
    constexpr int K9 = 9 * CIN;
    constexpr int WPLANE = COUT * K9;
    constexpr int IPLANE = 256 * HIN * WIN * CIN;
    constexpr int OPLANE = 256 * HO * WO * COUT;
    constexpr int AST = 72;                  // padded row stride (144 B)
    constexpr int APL = 128 * AST;           // A plane: 128 pixel rows
    constexpr int BPL = 128 * AST;           // B plane: 128 cout rows
    constexpr uint32_t BUF = (uint32_t)(2 * APL + 2 * BPL) * 2;  // 73728 B / stage

    extern __shared__ __align__(16) __half sm[];

    const int tid = threadIdx.x;
    const int wid = tid >> 5, lid = tid & 31;
    const int g = lid >> 2, t = lid & 3;
    const int wpx = wid >> 2, wco = wid & 3;     // 4 px-quarters x 4 co-quarters
    const int pixBase = blockIdx.x * 128;
    const int coBase  = blockIdx.y * 128;

    const uint32_t smb = (uint32_t)__cvta_generic_to_shared(sm);
    const int arow = (lid & 7) + ((lid >> 3) & 1) * 8;
    const int achk = ((lid >> 4) & 1) * 8;
    const int brow = (lid & 7) + ((lid >> 4) & 1) * 8;
    const int bchk = ((lid >> 3) & 1) * 8;
    const uint32_t aAddr0 = smb + (uint32_t)(((wpx * 32 + arow) * AST + achk) * 2);
    const uint32_t bAddr0 = smb + (uint32_t)(2 * APL * 2) +
                            (uint32_t)(((wco * 32 + brow) * AST + bchk) * 2);

    // staging: 2 A planes x 128 rows + 2 B variants x 128 rows = 512 row jobs
    auto stage = [&](int s, uint32_t bofs) {
        const int tap = s / CG, cg = s - tap * CG;
        const int ky = tap / 3, kx = tap - ky * 3;
        const int c0 = cg * 64;
        const int j = tid;   // exactly one job per thread (512 jobs / 512 thr)
        if (j < 256) {
            const int pl = j >> 7, row = j & 127;
            const int gp = pixBase + row;
            const int n  = gp / PIX;
            const int r  = gp - n * PIX;
            const int oy = r / WO, ox = r - (r / WO) * WO;
            const int iy = oy * S - 1 + ky, ix = ox * S - 1 + kx;
            uint32_t dst = smb + bofs + (uint32_t)((pl * APL + row * AST) * 2);
            const bool ok = (iy >= 0 && iy < HIN && ix >= 0 && ix < WIN);
            const __half* src = ok
                ? pin + (size_t)pl * IPLANE + ((size_t)(n * HIN + iy) * WIN + ix) * CIN + c0
                : pin;
            const int sz = ok ? 16 : 0;
            #pragma unroll
            for (int q = 0; q < 8; q++)
                cpa16(dst + q * 16, src + q * 8, sz);
        } else {
            const int jj = j - 256;
            const int var = jj >> 7, row = jj & 127;
            const __half* src = wq + (size_t)var * WPLANE +
                                (size_t)(coBase + row) * K9 + tap * CIN + c0;
            uint32_t dst = smb + bofs + (uint32_t)((2 * APL + var * BPL + row * AST) * 2);
            #pragma unroll
            for (int q = 0; q < 8; q++)
                cpa16(dst + q * 16, src + q * 8, 16);
        }
    };

    float accM[2][4][4], accV[2][4][4];
    #pragma unroll
    for (int mt = 0; mt < 2; mt++)
        #pragma unroll
        for (int nt = 0; nt < 4; nt++)
            #pragma unroll
            for (int e = 0; e < 4; e++) { accM[mt][nt][e] = 0.f; accV[mt][nt][e] = 0.f; }

    // one k-step of compute on buffer bofs
    auto compute_ks = [&](int ks, uint32_t bofs) {
        const uint32_t ksb = (uint32_t)(ks * 32) + bofs;
        uint32_t bm[2][4], bv[2][4];
        #pragma unroll
        for (int ntp = 0; ntp < 2; ntp++) {
            const uint32_t b0 = bAddr0 + (uint32_t)(ntp * 16 * AST * 2) + ksb;
            LDMX4(bm[ntp], b0);
            LDMX4(bv[ntp], b0 + (uint32_t)(BPL * 2));
        }
        uint32_t ax[2][4], as_[2][4];
        #pragma unroll
        for (int mt = 0; mt < 2; mt++) {
            const uint32_t a0 = aAddr0 + (uint32_t)(mt * 16 * AST * 2) + ksb;
            LDMX4(ax[mt], a0);
            LDMX4(as_[mt], a0 + (uint32_t)(APL * 2));
        }
        #pragma unroll
        for (int mt = 0; mt < 2; mt++)
            #pragma unroll
            for (int nt = 0; nt < 4; nt++) {
                const int ntp = nt >> 1, o = (nt & 1) * 2;
                MMA16816(accM[mt][nt], ax[mt],  &bm[ntp][o]);
                MMA16816(accV[mt][nt], as_[mt], &bv[ntp][o]);
            }
    };

    stage(0, 0);
    cpa_commit();

    #pragma unroll 1
    for (int s = 0; s < NS; s++) {
        cpa_wait0();          // buffer s ready (only group s pending)
        __syncthreads();
        const uint32_t bofs = (uint32_t)(s & 1) * BUF;

        compute_ks(0, bofs);
        if (s + 1 < NS) {     // overlap next-stage issue with remaining compute
            stage(s + 1, (uint32_t)((s + 1) & 1) * BUF);
            cpa_commit();
        }
        compute_ks(1, bofs);
        compute_ks(2, bofs);
        compute_ks(3, bofs);
        __syncthreads();      // all warps done with buffer s before it is restaged
    }

    // ---- epilogue ----
    #pragma unroll
    for (int mt = 0; mt < 2; mt++)
        #pragma unroll
        for (int nt = 0; nt < 4; nt++) {
            const int co0 = coBase + wco * 32 + nt * 8 + 2 * t;
            const float b0 = bias[co0], b1 = bias[co0 + 1];
            #pragma unroll
            for (int h2 = 0; h2 < 2; h2++) {
                const int gp = pixBase + wpx * 32 + mt * 16 + g + h2 * 8;
                float m0 = accM[mt][nt][2 * h2]     + b0;
                float m1 = accM[mt][nt][2 * h2 + 1] + b1;
                float v0 = accV[mt][nt][2 * h2];
                float v1 = accV[mt][nt][2 * h2 + 1];
                const int n = gp / PIX;
                const int r = gp - n * PIX;
                const int oy = r / WO, ox = r - (r / WO) * WO;
                if (LAST) {
                    int o0 = ((n * COUT + co0) * HO + oy) * WO + ox;
                    int o1 = o0 + HO * WO;
                    zout[o0] = m0 + sqrtf(v0 + EPS) * noise[o0];
                    zout[o1] = m1 + sqrtf(v1 + EPS) * noise[o1];
                } else {
                    float h0 = erff(m0 * rsqrtf(2.f * (v0 + EPS)));
                    float h1 = erff(m1 * rsqrtf(2.f * (v1 + EPS)));
                    int oi = ((n * HO + oy) * WO + ox) * COUT + co0;
                    *(uint32_t*)&pout[oi]          = pkh2(h0, h1);
                    *(uint32_t*)&pout[OPLANE + oi] = pkh2(h0 * h0, h1 * h1);
                }
            }
        }
}

// ================= batchnorm ===================================================
__global__ void bn_stats(const float* __restrict__ z, const float* __restrict__ gamma,
                         const float* __restrict__ beta, float* __restrict__ scale,
                         float* __restrict__ shift)
{
    __shared__ double ssum[256], ssq[256];
    int c = blockIdx.x, t = threadIdx.x;
    double s = 0.0, s2 = 0.0;
    for (int i = t; i < 4096; i += 256) {
        int n = i >> 4, qq = i & 15;
        float v = z[(n * 512 + c) * 16 + qq];
        s += v; s2 += (double)v * v;
    }
    ssum[t] = s; ssq[t] = s2;
    __syncthreads();
    for (int off = 128; off > 0; off >>= 1) {
        if (t < off) { ssum[t] += ssum[t + off]; ssq[t] += ssq[t + off]; }
        __syncthreads();
    }
    if (t == 0) {
        double mean = ssum[0] / 4096.0;
        double var  = ssq[0] / 4096.0 - mean * mean;
        float sc = gamma[c] * rsqrtf((float)var + EPS);
        scale[c] = sc;
        shift[c] = beta[c] - (float)mean * sc;
    }
}

__global__ void bn_norm(const float* __restrict__ z, const float* __restrict__ scale,
                        const float* __restrict__ shift, float* __restrict__ out)
{
    int idx = blockIdx.x * blockDim.x + threadIdx.x;
    if (idx < 256 * 8192) {
        int c = (idx >> 4) & 511;
        float v = z[idx] * scale[c] + shift[c];
        out[idx] = v > 0.f ? v : 0.f;
    }
}

// ================= FC1 v2: split-K, k-major smem, f32x2 ========================
// grid (16 nBlk, 4 mBlk, 2 kSplit), 256 thr. Tile 64x64, K-half = 4096.
// Partials (exact fp32) to P[ks][m*1024+n]; fc1_post sums + bias + relu.
__global__ void __launch_bounds__(256)
fc1_kernel(const float* __restrict__ A, const float* __restrict__ W,
           float* __restrict__ P)
{
    constexpr int ST = 68;                 // padded k-major row stride (floats)
    __shared__ __align__(16) float As[32 * ST];
    __shared__ __align__(16) float Ws[32 * ST];
    const int t = threadIdx.x;
    const int nBlk = blockIdx.x * 64, mBlk = blockIdx.y * 64;
    const int kBase = blockIdx.z * 4096;
    const int msub = (t % 16) * 4, nsub = (t / 16) * 4;

    unsigned long long acc[2][4];
    #pragma unroll
    for (int p = 0; p < 2; p++)
        #pragma unroll
        for (int j = 0; j < 4; j++) acc[p][j] = 0ull;

    #pragma unroll 1
    for (int k0 = 0; k0 < 4096; k0 += 32) {
        // stage transposed: kk-major rows (coalesced global read, scattered store)
        for (int i = t; i < 2048; i += 256) {
            int kk = i & 31, row = i >> 5;
            As[kk * ST + row] = A[(size_t)(mBlk + row) * 8192 + kBase + k0 + kk];
            Ws[kk * ST + row] = W[(size_t)(nBlk + row) * 8192 + kBase + k0 + kk];
        }
        __syncthreads();
        #pragma unroll
        for (int kk = 0; kk < 32; kk++) {
            float4 a4 = *reinterpret_cast<const float4*>(&As[kk * ST + msub]);
            float4 w4 = *reinterpret_cast<const float4*>(&Ws[kk * ST + nsub]);
            unsigned long long ap0 = pkf2(a4.x, a4.y);
            unsigned long long ap1 = pkf2(a4.z, a4.w);
            unsigned long long w0 = bcast2(w4.x), w1 = bcast2(w4.y);
            unsigned long long w2 = bcast2(w4.z), w3 = bcast2(w4.w);
            fma2(acc[0][0], ap0, w0); fma2(acc[1][0], ap1, w0);
            fma2(acc[0][1], ap0, w1); fma2(acc[1][1], ap1, w1);
            fma2(acc[0][2], ap0, w2); fma2(acc[1][2], ap1, w2);
            fma2(acc[0][3], ap0, w3); fma2(acc[1][3], ap1, w3);
        }
        __syncthreads();
    }

    float* out = P + (size_t)blockIdx.z * 262144;
    #pragma unroll
    for (int p = 0; p < 2; p++)
        #pragma unroll
        for (int j = 0; j < 4; j++) {
            float lo, hi;
            unpack2(acc[p][j], lo, hi);
            int m0 = mBlk + msub + 2 * p;
            int n  = nBlk + nsub + j;
            out[(size_t)m0 * 1024 + n]       = lo;
            out[(size_t)(m0 + 1) * 1024 + n] = hi;
        }
}

__global__ void fc1_post(const float* __restrict__ P, const float* __restrict__ bias,
                         float* __restrict__ C)
{
    int i = blockIdx.x * 256 + threadIdx.x;
    if (i < 262144) {
        float v = P[i] + P[262144 + i] + bias[i & 1023];
        C[i] = v > 0.f ? v : 0.f;
    }
}

// ================= FC2: [256,1024] x [10,1024]^T + bias ========================
__global__ void fc2_kernel(const float* __restrict__ A, const float* __restrict__ W,
                           const float* __restrict__ bias, float* __restrict__ out)
{
    int idx = blockIdx.x * blockDim.x + threadIdx.x;
    if (idx >= 2560) return;
    int n = idx / 10, j = idx - n * 10;
    const float* a = A + n * 1024;
    const float* w = W + j * 1024;
    float s = bias[j];
    for (int k = 0; k < 1024; k += 4)
        s += a[k] * w[k] + a[k + 1] * w[k + 1] + a[k + 2] * w[k + 2] + a[k + 3] * w[k + 3];
    out[idx] = s;
}

// ================= launch ======================================================
extern "C" void kernel_launch(void* const* d_in, const int* in_sizes, int n_in,
                              void* d_out, int out_size)
{
    (void)in_sizes; (void)n_in; (void)out_size;
    const float* x = (const float*)d_in[0];
    const float* a[6]  = {(const float*)d_in[1],  (const float*)d_in[4],  (const float*)d_in[7],
                          (const float*)d_in[10], (const float*)d_in[13], (const float*)d_in[16]};
    const float* bt[6] = {(const float*)d_in[2],  (const float*)d_in[5],  (const float*)d_in[8],
                          (const float*)d_in[11], (const float*)d_in[14], (const float*)d_in[17]};
    const float* cb[6] = {(const float*)d_in[3],  (const float*)d_in[6],  (const float*)d_in[9],
                          (const float*)d_in[12], (const float*)d_in[15], (const float*)d_in[18]};
    const float* gamma = (const float*)d_in[19];
    const float* beta  = (const float*)d_in[20];
    const float* fc1w  = (const float*)d_in[21];
    const float* fc1b  = (const float*)d_in[22];
    const float* fc2w  = (const float*)d_in[23];
    const float* fc2b  = (const float*)d_in[24];
    const float* noise = (const float*)d_in[25];

    __half *w2q, *w3q, *w4q, *w5q, *w6q, *p1, *p2, *p3, *p4, *p5;
    cudaGetSymbolAddress((void**)&w2q, g_w2q);
    cudaGetSymbolAddress((void**)&w3q, g_w3q);
    cudaGetSymbolAddress((void**)&w4q, g_w4q);
    cudaGetSymbolAddress((void**)&w5q, g_w5q);
    cudaGetSymbolAddress((void**)&w6q, g_w6q);
    cudaGetSymbolAddress((void**)&p1, g_p1);
    cudaGetSymbolAddress((void**)&p2, g_p2);
    cudaGetSymbolAddress((void**)&p3, g_p3);
    cudaGetSymbolAddress((void**)&p4, g_p4);
    cudaGetSymbolAddress((void**)&p5, g_p5);

    float *z6, *zbn, *fc1p, *fc1o, *scale, *shift;
    cudaGetSymbolAddress((void**)&z6,  g_z6);
    cudaGetSymbolAddress((void**)&zbn, g_zbn);
    cudaGetSymbolAddress((void**)&fc1p, g_fc1p);
    cudaGetSymbolAddress((void**)&fc1o, g_fc1o);
    cudaGetSymbolAddress((void**)&scale, g_bnscale);
    cudaGetSymbolAddress((void**)&shift, g_bnshift);

    constexpr int SMEM_MMA = 2 * (2 * 128 + 2 * 128) * 72 * 2;   // 147456 B
    auto k2 = conv_mma<128, 128, 32, 32, 2, false>;
    auto k3 = conv_mma<128, 256, 16, 16, 1, false>;
    auto k4 = conv_mma<256, 256, 16, 16, 2, false>;
    auto k5 = conv_mma<256, 512, 8,  8,  1, false>;
    auto k6 = conv_mma<512, 512, 8,  8,  2, true>;
    cudaFuncSetAttribute(k2, cudaFuncAttributeMaxDynamicSharedMemorySize, SMEM_MMA);
    cudaFuncSetAttribute(k3, cudaFuncAttributeMaxDynamicSharedMemorySize, SMEM_MMA);
    cudaFuncSetAttribute(k4, cudaFuncAttributeMaxDynamicSharedMemorySize, SMEM_MMA);
    cudaFuncSetAttribute(k5, cudaFuncAttributeMaxDynamicSharedMemorySize, SMEM_MMA);
    cudaFuncSetAttribute(k6, cudaFuncAttributeMaxDynamicSharedMemorySize, SMEM_MMA);

    // 0: weight prep
    prepw<<<(4574592 + 255) / 256, 256>>>(a[0], bt[0], a[1], bt[1], a[2], bt[2],
                                          a[3], bt[3], a[4], bt[4], a[5], bt[5]);
    // 1: L1 SIMT -> planes p1
    conv1<<<dim3(16, 4, 128), 128>>>(x, cb[0], p1);
    // 2: L2 128->128, 32->16, s2: 65536 px -> 512 tiles, COUT=128 -> 1 co-block
    k2<<<dim3(512, 1), 512, SMEM_MMA>>>(w2q, p1, cb[1], p2, nullptr, nullptr);
    // 3: L3 128->256, 16x16: 512 tiles x 2 co-blocks
    k3<<<dim3(512, 2), 512, SMEM_MMA>>>(w3q, p2, cb[2], p3, nullptr, nullptr);
    // 4: L4 256->256, 16->8, s2: 128 tiles x 2 co-blocks
    k4<<<dim3(128, 2), 512, SMEM_MMA>>>(w4q, p3, cb[3], p4, nullptr, nullptr);
    // 5: L5 256->512, 8x8: 128 tiles x 4 co-blocks  <- ncu -s 5 target
    k5<<<dim3(128, 4), 512, SMEM_MMA>>>(w5q, p4, cb[4], p5, nullptr, nullptr);
    // 6: L6 512->512, 8->4, s2, sampled: 32 tiles x 4 co-blocks
    k6<<<dim3(32, 4), 512, SMEM_MMA>>>(w6q, p5, cb[5], nullptr, z6, noise);

    bn_stats<<<512, 256>>>(z6, gamma, beta, scale, shift);
    bn_norm<<<(2097152 + 255) / 256, 256>>>(z6, scale, shift, zbn);
    fc1_kernel<<<dim3(16, 4, 2), 256>>>(zbn, fc1w, fc1p);
    fc1_post<<<(262144 + 255) / 256, 256>>>(fc1p, fc1b, fc1o);
    fc2_kernel<<<(2560 + 127) / 128, 128>>>(fc1o, fc2w, fc2b, (float*)d_out);
}